// round 10
// baseline (speedup 1.0000x reference)
#include <cuda_runtime.h>
#include <cuda_bf16.h>
#include <math.h>
#include <cstdint>

// Problem constants
#define BATCH   2
#define SLEN    2048
#define DMODEL  1024
#define NHEADS  16
#define HEADDIM 64
#define NROWS   (BATCH * SLEN)      // 4096
#define NGROUPS (BATCH * NHEADS)    // 32 reshaped "heads"

// Scratch (allocation-free rule: __device__ globals)
__device__ float g_P[NROWS * DMODEL];
__device__ __nv_bfloat16 g_Qb[NROWS * DMODEL];
__device__ __nv_bfloat16 g_Kb[NROWS * DMODEL];
__device__ __nv_bfloat16 g_Vb[NROWS * DMODEL];
__device__ __nv_bfloat16 g_Ob[NROWS * DMODEL];
__device__ __nv_bfloat16 g_Qin[NROWS * DMODEL];
__device__ __nv_bfloat16 g_Kin[NROWS * DMODEL];
__device__ __nv_bfloat16 g_Vin[NROWS * DMODEL];
__device__ __nv_bfloat16 g_WqT[DMODEL * DMODEL];
__device__ __nv_bfloat16 g_WkT[DMODEL * DMODEL];
__device__ __nv_bfloat16 g_WvT[DMODEL * DMODEL];
__device__ __nv_bfloat16 g_WoT[DMODEL * DMODEL];

// ---------------------------------------------------------------------------
// Helpers (sm_80+ only — compute_103 rejects 'a'-gated PTX like tcgen05)
// ---------------------------------------------------------------------------
__device__ __forceinline__ uint32_t smem_u32(const void* p) {
    uint32_t a;
    asm("{ .reg .u64 t; cvta.to.shared.u64 t, %1; cvt.u32.u64 %0, t; }"
        : "=r"(a) : "l"(p));
    return a;
}

__device__ __forceinline__ void cp_async16(uint32_t saddr, const void* gaddr) {
    asm volatile("cp.async.cg.shared.global [%0], [%1], 16;"
                 :: "r"(saddr), "l"(gaddr) : "memory");
}
#define CP_COMMIT() asm volatile("cp.async.commit_group;" ::: "memory")
#define CP_WAIT1()  asm volatile("cp.async.wait_group 1;" ::: "memory")

__device__ __forceinline__ void mma_bf16(float* d, const uint32_t* a, const uint32_t* b) {
    asm volatile(
        "mma.sync.aligned.m16n8k16.row.col.f32.bf16.bf16.f32 "
        "{%0,%1,%2,%3}, {%4,%5,%6,%7}, {%8,%9}, {%0,%1,%2,%3};"
        : "+f"(d[0]), "+f"(d[1]), "+f"(d[2]), "+f"(d[3])
        : "r"(a[0]), "r"(a[1]), "r"(a[2]), "r"(a[3]), "r"(b[0]), "r"(b[1]));
}

__device__ __forceinline__ void ldsm_x4(uint32_t* r, uint32_t saddr) {
    asm volatile("ldmatrix.sync.aligned.m8n8.x4.shared.b16 {%0,%1,%2,%3}, [%4];"
                 : "=r"(r[0]), "=r"(r[1]), "=r"(r[2]), "=r"(r[3]) : "r"(saddr));
}

__device__ __forceinline__ void ldsm_x4_trans(uint32_t* r, uint32_t saddr) {
    asm volatile("ldmatrix.sync.aligned.m8n8.x4.trans.shared.b16 {%0,%1,%2,%3}, [%4];"
                 : "=r"(r[0]), "=r"(r[1]), "=r"(r[2]), "=r"(r[3]) : "r"(saddr));
}

__device__ __forceinline__ uint32_t pack_bf16x2(float lo, float hi) {
    __nv_bfloat162 h = __floats2bfloat162_rn(lo, hi);
    return *reinterpret_cast<uint32_t*>(&h);
}

// ---------------------------------------------------------------------------
// Fused fp32 -> bf16 conversion of q/k/v inputs (blockIdx.y selects tensor)
// ---------------------------------------------------------------------------
__global__ __launch_bounds__(256) void cvt_bf16_fused(
    const float* __restrict__ x0, const float* __restrict__ x1,
    const float* __restrict__ x2,
    __nv_bfloat16* __restrict__ y0, __nv_bfloat16* __restrict__ y1,
    __nv_bfloat16* __restrict__ y2)
{
    const int z = blockIdx.y;
    const float* x = (z == 0) ? x0 : (z == 1) ? x1 : x2;
    __nv_bfloat16* y = (z == 0) ? y0 : (z == 1) ? y1 : y2;
    const size_t i = ((size_t)blockIdx.x * 256 + threadIdx.x) * 8;
    float4 a = *(const float4*)(x + i);
    float4 b = *(const float4*)(x + i + 4);
    __nv_bfloat162* yp = reinterpret_cast<__nv_bfloat162*>(y + i);
    yp[0] = __floats2bfloat162_rn(a.x, a.y);
    yp[1] = __floats2bfloat162_rn(a.z, a.w);
    yp[2] = __floats2bfloat162_rn(b.x, b.y);
    yp[3] = __floats2bfloat162_rn(b.z, b.w);
}

// ---------------------------------------------------------------------------
// Weight transpose (fp32 -> bf16): Wt[n][k] = bf16(W[k][n]), 1024x1024
// ---------------------------------------------------------------------------
__global__ __launch_bounds__(256) void transpose1024_bf16(
    const float* __restrict__ W, __nv_bfloat16* __restrict__ Wt)
{
    __shared__ float t[32][33];
    const int bx = blockIdx.x * 32, by = blockIdx.y * 32;
    const int x = threadIdx.x, y = threadIdx.y;   // 32 x 8
#pragma unroll
    for (int i = 0; i < 32; i += 8)
        t[y + i][x] = W[(size_t)(by + y + i) * DMODEL + bx + x];
    __syncthreads();
#pragma unroll
    for (int i = 0; i < 32; i += 8)
        Wt[(size_t)(bx + y + i) * DMODEL + by + x] = __float2bfloat16_rn(t[x][y + i]);
}

// ---------------------------------------------------------------------------
// HMMA bf16 GEMM (R8-validated 2-stage pipeline): CTA 128x128, BK=64,
// 8 warps (4x2), warp 32x64. Smem 73728 B => 3 CTAs/SM (occupancy is the
// binding constraint — R9's deeper pipeline at 110 KB regressed).
// ---------------------------------------------------------------------------
#define KSW 36
#define TILE_WORDS (128 * KSW)
#define GEMM_SMEM (4 * TILE_WORDS * 4)   // 73728 B

__global__ __launch_bounds__(256) void gemm_bf16_qkv(
    const __nv_bfloat16* __restrict__ A0, const __nv_bfloat16* __restrict__ A1,
    const __nv_bfloat16* __restrict__ A2,
    const __nv_bfloat16* __restrict__ B0, const __nv_bfloat16* __restrict__ B1,
    const __nv_bfloat16* __restrict__ B2,
    __nv_bfloat16* __restrict__ C0, __nv_bfloat16* __restrict__ C1,
    __nv_bfloat16* __restrict__ C2, int M, int N, int K)
{
    extern __shared__ uint32_t shw[];
    uint32_t* sA[2] = { shw,              shw + 2 * TILE_WORDS };
    uint32_t* sB[2] = { shw + TILE_WORDS, shw + 3 * TILE_WORDS };

    const int z = blockIdx.z;
    const __nv_bfloat16* A = (z == 0) ? A0 : (z == 1) ? A1 : A2;
    const __nv_bfloat16* Bt = (z == 0) ? B0 : (z == 1) ? B1 : B2;
    __nv_bfloat16* C = (z == 0) ? C0 : (z == 1) ? C1 : C2;

    const int tid = threadIdx.x;
    const int wid = tid >> 5;
    const int lane = tid & 31;
    const int mb = (wid & 3) * 32;
    const int nb = (wid >> 2) * 64;
    const int g = lane >> 2;
    const int t = lane & 3;
    const int m0 = blockIdx.y * 128;
    const int n0 = blockIdx.x * 128;

    const int quad = lane >> 3;
    const int within = lane & 7;
    const int arow = (quad & 1) * 8 + within;
    const int acol = (quad >> 1) * 4;
    const int brow = (quad >> 1) * 8 + within;
    const int bcol = (quad & 1) * 4;

    const uint32_t aoff0 = (uint32_t)((mb + arow) * KSW + acol) * 4u;
    const uint32_t aoff1 = (uint32_t)((mb + 16 + arow) * KSW + acol) * 4u;
    uint32_t boff[4];
#pragma unroll
    for (int ntp = 0; ntp < 4; ntp++)
        boff[ntp] = (uint32_t)((nb + ntp * 16 + brow) * KSW + bcol) * 4u;

    const uint32_t saw[2] = { smem_u32(sA[0]), smem_u32(sA[1]) };
    const uint32_t sbw[2] = { smem_u32(sB[0]), smem_u32(sB[1]) };

    float acc[2][8][4];
#pragma unroll
    for (int i = 0; i < 2; i++)
#pragma unroll
        for (int j = 0; j < 8; j++)
#pragma unroll
            for (int q = 0; q < 4; q++) acc[i][j][q] = 0.f;

    const int NCH = K / 64;

    auto issue = [&](int c, int b) {
        const __nv_bfloat16* Ag = A + (size_t)m0 * K + (size_t)c * 64;
        const __nv_bfloat16* Bg = Bt + (size_t)n0 * K + (size_t)c * 64;
#pragma unroll
        for (int i = 0; i < 4; i++) {
            const int u = tid + 256 * i;
            const int row = u >> 3;
            const int seg = u & 7;
            const uint32_t so = (uint32_t)(row * KSW + seg * 4) * 4u;
            cp_async16(saw[b] + so, Ag + (size_t)row * K + seg * 8);
            cp_async16(sbw[b] + so, Bg + (size_t)row * K + seg * 8);
        }
        CP_COMMIT();
    };

    issue(0, 0);
    issue(1, 1);

    for (int c = 0; c < NCH; c++) {
        const int b = c & 1;
        CP_WAIT1();
        __syncthreads();
#pragma unroll
        for (int s = 0; s < 4; s++) {
            const uint32_t ks = (uint32_t)s * 32u;
            uint32_t af0[4], af1[4];
            ldsm_x4(af0, saw[b] + aoff0 + ks);
            ldsm_x4(af1, saw[b] + aoff1 + ks);
#pragma unroll
            for (int ntp = 0; ntp < 4; ntp++) {
                uint32_t bq[4];
                ldsm_x4(bq, sbw[b] + boff[ntp] + ks);
                mma_bf16(acc[0][2 * ntp],     af0, bq);
                mma_bf16(acc[1][2 * ntp],     af1, bq);
                mma_bf16(acc[0][2 * ntp + 1], af0, bq + 2);
                mma_bf16(acc[1][2 * ntp + 1], af1, bq + 2);
            }
        }
        __syncthreads();
        if (c + 2 < NCH) issue(c + 2, b);
        else CP_COMMIT();
    }

#pragma unroll
    for (int mt = 0; mt < 2; mt++) {
        const int r = m0 + mb + mt * 16 + g;
#pragma unroll
        for (int nt = 0; nt < 8; nt++) {
            const int cx = n0 + nb + nt * 8 + 2 * t;
            uint32_t w0 = pack_bf16x2(acc[mt][nt][0], acc[mt][nt][1]);
            uint32_t w1 = pack_bf16x2(acc[mt][nt][2], acc[mt][nt][3]);
            *reinterpret_cast<uint32_t*>(C + (size_t)r * N + cx) = w0;
            *reinterpret_cast<uint32_t*>(C + (size_t)(r + 8) * N + cx) = w1;
        }
    }
}

__global__ __launch_bounds__(256) void gemm_bf16_out(
    const __nv_bfloat16* __restrict__ A, const __nv_bfloat16* __restrict__ Bt,
    const float* __restrict__ bias, float* __restrict__ C,
    int M, int N, int K)
{
    extern __shared__ uint32_t shw[];
    uint32_t* sA[2] = { shw,              shw + 2 * TILE_WORDS };
    uint32_t* sB[2] = { shw + TILE_WORDS, shw + 3 * TILE_WORDS };

    const int tid = threadIdx.x;
    const int wid = tid >> 5;
    const int lane = tid & 31;
    const int mb = (wid & 3) * 32;
    const int nb = (wid >> 2) * 64;
    const int g = lane >> 2;
    const int t = lane & 3;
    const int m0 = blockIdx.y * 128;
    const int n0 = blockIdx.x * 128;

    const int quad = lane >> 3;
    const int within = lane & 7;
    const int arow = (quad & 1) * 8 + within;
    const int acol = (quad >> 1) * 4;
    const int brow = (quad >> 1) * 8 + within;
    const int bcol = (quad & 1) * 4;

    const uint32_t aoff0 = (uint32_t)((mb + arow) * KSW + acol) * 4u;
    const uint32_t aoff1 = (uint32_t)((mb + 16 + arow) * KSW + acol) * 4u;
    uint32_t boff[4];
#pragma unroll
    for (int ntp = 0; ntp < 4; ntp++)
        boff[ntp] = (uint32_t)((nb + ntp * 16 + brow) * KSW + bcol) * 4u;

    const uint32_t saw[2] = { smem_u32(sA[0]), smem_u32(sA[1]) };
    const uint32_t sbw[2] = { smem_u32(sB[0]), smem_u32(sB[1]) };

    float acc[2][8][4];
#pragma unroll
    for (int i = 0; i < 2; i++)
#pragma unroll
        for (int j = 0; j < 8; j++)
#pragma unroll
            for (int q = 0; q < 4; q++) acc[i][j][q] = 0.f;

    const int NCH = K / 64;

    auto issue = [&](int c, int b) {
        const __nv_bfloat16* Ag = A + (size_t)m0 * K + (size_t)c * 64;
        const __nv_bfloat16* Bg = Bt + (size_t)n0 * K + (size_t)c * 64;
#pragma unroll
        for (int i = 0; i < 4; i++) {
            const int u = tid + 256 * i;
            const int row = u >> 3;
            const int seg = u & 7;
            const uint32_t so = (uint32_t)(row * KSW + seg * 4) * 4u;
            cp_async16(saw[b] + so, Ag + (size_t)row * K + seg * 8);
            cp_async16(sbw[b] + so, Bg + (size_t)row * K + seg * 8);
        }
        CP_COMMIT();
    };

    issue(0, 0);
    issue(1, 1);

    for (int c = 0; c < NCH; c++) {
        const int b = c & 1;
        CP_WAIT1();
        __syncthreads();
#pragma unroll
        for (int s = 0; s < 4; s++) {
            const uint32_t ks = (uint32_t)s * 32u;
            uint32_t af0[4], af1[4];
            ldsm_x4(af0, saw[b] + aoff0 + ks);
            ldsm_x4(af1, saw[b] + aoff1 + ks);
#pragma unroll
            for (int ntp = 0; ntp < 4; ntp++) {
                uint32_t bq[4];
                ldsm_x4(bq, sbw[b] + boff[ntp] + ks);
                mma_bf16(acc[0][2 * ntp],     af0, bq);
                mma_bf16(acc[1][2 * ntp],     af1, bq);
                mma_bf16(acc[0][2 * ntp + 1], af0, bq + 2);
                mma_bf16(acc[1][2 * ntp + 1], af1, bq + 2);
            }
        }
        __syncthreads();
        if (c + 2 < NCH) issue(c + 2, b);
        else CP_COMMIT();
    }

#pragma unroll
    for (int mt = 0; mt < 2; mt++) {
        const int r = m0 + mb + mt * 16 + g;
#pragma unroll
        for (int nt = 0; nt < 8; nt++) {
            const int cx = n0 + nb + nt * 8 + 2 * t;
            const float b0 = __ldg(&bias[cx]);
            const float b1 = __ldg(&bias[cx + 1]);
            float2 v0, v1;
            v0.x = acc[mt][nt][0] + b0; v0.y = acc[mt][nt][1] + b1;
            v1.x = acc[mt][nt][2] + b0; v1.y = acc[mt][nt][3] + b1;
            *(float2*)(C + (size_t)r * N + cx) = v0;
            *(float2*)(C + (size_t)(r + 8) * N + cx) = v1;
        }
    }
}

// ---------------------------------------------------------------------------
// bf16 HMMA flash attention (R8-validated 2-stage pipeline; V row-major with
// ldmatrix.x4.trans for the PV B-operand — validated bit-identical in R9).
// Q,K,V bf16 [32][2048][64]. CTA: 128 Q rows x 1 group, 8 warps.
// Smem 55296 B => 4 CTAs/SM.
// ---------------------------------------------------------------------------
#define AKW 36
#define ATT_TILE (64 * AKW)
#define ATT_SMEM ((4 * ATT_TILE + 128 * AKW) * 4)   // 55296 B

__global__ __launch_bounds__(256) void attn_bf16(
    const __nv_bfloat16* __restrict__ Q, const __nv_bfloat16* __restrict__ K,
    const __nv_bfloat16* __restrict__ V, const unsigned char* __restrict__ mask,
    __nv_bfloat16* __restrict__ O)
{
    extern __shared__ uint32_t smw[];
    uint32_t* sP = smw + 4 * ATT_TILE;   // [128][AKW]

    const int tid = threadIdx.x;
    const int wid = tid >> 5;
    const int lane = tid & 31;
    const int gq = lane >> 2;
    const int t = lane & 3;
    const int qb = blockIdx.x;
    const int grp = blockIdx.y;
    const int r0 = wid * 16;

    const int quad = lane >> 3;
    const int within = lane & 7;
    const int arow = (quad & 1) * 8 + within;
    const int acol = (quad >> 1) * 4;
    const int brow = (quad >> 1) * 8 + within;   // K (non-trans)
    const int bcol = (quad & 1) * 4;
    const int vrow = (quad & 1) * 8 + within;    // V (trans): row = key-as-k
    const int vcol = (quad >> 1) * 8;            // dim block

    uint32_t boffK[4], boffV[4];
#pragma unroll
    for (int ntp = 0; ntp < 4; ntp++) {
        boffK[ntp] = (uint32_t)((ntp * 16 + brow) * AKW + bcol) * 4u;
        boffV[ntp] = (uint32_t)(vrow * AKW) * 4u + (uint32_t)(ntp * 16 + vcol) * 2u;
    }

    const uint32_t skw[2] = { smem_u32(smw), smem_u32(smw + ATT_TILE) };
    const uint32_t svw[2] = { smem_u32(smw + 2 * ATT_TILE), smem_u32(smw + 3 * ATT_TILE) };

    const __nv_bfloat16* Qg = Q + ((size_t)grp * SLEN + qb * 128 + r0) * HEADDIM;
    const __nv_bfloat16* Kg = K + (size_t)grp * SLEN * HEADDIM;
    const __nv_bfloat16* Vg = V + (size_t)grp * SLEN * HEADDIM;
    const unsigned char* mrow =
        mask + (size_t)(grp % BATCH) * SLEN * SLEN + (size_t)(qb * 128 + r0) * SLEN;

    auto issue = [&](int kt, int b) {
#pragma unroll
        for (int i = 0; i < 2; i++) {
            const int u = tid + 256 * i;
            const int row = u >> 3;
            const int seg = u & 7;
            const uint32_t so = (uint32_t)(row * AKW + seg * 4) * 4u;
            cp_async16(skw[b] + so, Kg + (size_t)(kt * 64 + row) * HEADDIM + seg * 8);
            cp_async16(svw[b] + so, Vg + (size_t)(kt * 64 + row) * HEADDIM + seg * 8);
        }
        CP_COMMIT();
    };

    // ---- Stage Q (warp-private rows of sP), build persistent A fragments
    uint32_t* sQw = sP + r0 * AKW;
    const uint32_t spw_addr = smem_u32(sQw) + (uint32_t)(arow * AKW + acol) * 4u;
    {
        const int row = lane >> 1;
        const int cs = (lane & 1) * 16;
#pragma unroll
        for (int j = 0; j < 4; j++) {
            uint4 v = *(const uint4*)(Qg + (size_t)row * HEADDIM + (cs + j * 4) * 2);
            *(uint4*)&sQw[row * AKW + cs + j * 4] = v;
        }
    }
    __syncwarp();
    uint32_t qf[4][4];
#pragma unroll
    for (int s = 0; s < 4; s++)
        ldsm_x4(qf[s], spw_addr + (uint32_t)s * 32u);
    __syncthreads();   // Q fragments captured before sP reused for P

    issue(0, 0);
    issue(1, 1);

    float oacc[8][4];
#pragma unroll
    for (int nt = 0; nt < 8; nt++)
#pragma unroll
        for (int q = 0; q < 4; q++) oacc[nt][q] = 0.f;
    float mA = -INFINITY, mB = -INFINITY, lA = 0.f, lB = 0.f;

    const float scale = 0.125f;
    uint32_t* sPw = sP + r0 * AKW;
    const int NT = SLEN / 64;

    for (int kt = 0; kt < NT; kt++) {
        const int b = kt & 1;
        CP_WAIT1();
        __syncthreads();

        // ---- S = Q K^T
        float sacc[8][4];
#pragma unroll
        for (int nt = 0; nt < 8; nt++)
#pragma unroll
            for (int q = 0; q < 4; q++) sacc[nt][q] = 0.f;
#pragma unroll
        for (int s = 0; s < 4; s++) {
            const uint32_t ks = (uint32_t)s * 32u;
#pragma unroll
            for (int ntp = 0; ntp < 4; ntp++) {
                uint32_t bq[4];
                ldsm_x4(bq, skw[b] + boffK[ntp] + ks);
                mma_bf16(sacc[2 * ntp],     qf[s], bq);
                mma_bf16(sacc[2 * ntp + 1], qf[s], bq + 2);
            }
        }

        // ---- Mask + scale
#pragma unroll
        for (int nt = 0; nt < 8; nt++) {
            const int cb = kt * 64 + nt * 8 + 2 * t;
            uchar2 ma = *(const uchar2*)(mrow + (size_t)gq * SLEN + cb);
            uchar2 mb2 = *(const uchar2*)(mrow + (size_t)(gq + 8) * SLEN + cb);
            sacc[nt][0] = ma.x ? -1e9f : sacc[nt][0] * scale;
            sacc[nt][1] = ma.y ? -1e9f : sacc[nt][1] * scale;
            sacc[nt][2] = mb2.x ? -1e9f : sacc[nt][2] * scale;
            sacc[nt][3] = mb2.y ? -1e9f : sacc[nt][3] * scale;
        }

        // ---- Online softmax
        float mxA = -INFINITY, mxB = -INFINITY;
#pragma unroll
        for (int nt = 0; nt < 8; nt++) {
            mxA = fmaxf(mxA, fmaxf(sacc[nt][0], sacc[nt][1]));
            mxB = fmaxf(mxB, fmaxf(sacc[nt][2], sacc[nt][3]));
        }
        mxA = fmaxf(mxA, __shfl_xor_sync(0xffffffffu, mxA, 1));
        mxA = fmaxf(mxA, __shfl_xor_sync(0xffffffffu, mxA, 2));
        mxB = fmaxf(mxB, __shfl_xor_sync(0xffffffffu, mxB, 1));
        mxB = fmaxf(mxB, __shfl_xor_sync(0xffffffffu, mxB, 2));

        const float mnA = fmaxf(mA, mxA);
        const float mnB = fmaxf(mB, mxB);
        const float cA = __expf(mA - mnA);
        const float cB = __expf(mB - mnB);
        float suA = 0.f, suB = 0.f;
#pragma unroll
        for (int nt = 0; nt < 8; nt++) {
            sacc[nt][0] = __expf(sacc[nt][0] - mnA);
            sacc[nt][1] = __expf(sacc[nt][1] - mnA);
            sacc[nt][2] = __expf(sacc[nt][2] - mnB);
            sacc[nt][3] = __expf(sacc[nt][3] - mnB);
            suA += sacc[nt][0] + sacc[nt][1];
            suB += sacc[nt][2] + sacc[nt][3];
        }
        suA += __shfl_xor_sync(0xffffffffu, suA, 1);
        suA += __shfl_xor_sync(0xffffffffu, suA, 2);
        suB += __shfl_xor_sync(0xffffffffu, suB, 1);
        suB += __shfl_xor_sync(0xffffffffu, suB, 2);
        lA = lA * cA + suA;
        lB = lB * cB + suB;
        mA = mnA;
        mB = mnB;
#pragma unroll
        for (int nt = 0; nt < 8; nt++) {
            oacc[nt][0] *= cA; oacc[nt][1] *= cA;
            oacc[nt][2] *= cB; oacc[nt][3] *= cB;
        }

        // ---- Stage P packed bf16x2 (warp-private rows)
#pragma unroll
        for (int nt = 0; nt < 8; nt++) {
            sPw[gq * AKW + nt * 4 + t]       = pack_bf16x2(sacc[nt][0], sacc[nt][1]);
            sPw[(gq + 8) * AKW + nt * 4 + t] = pack_bf16x2(sacc[nt][2], sacc[nt][3]);
        }
        __syncwarp();

        // ---- O += P V  (A=P ldmatrix; B=V row-major via ldmatrix.trans)
#pragma unroll
        for (int s = 0; s < 4; s++) {
            uint32_t af[4];
            ldsm_x4(af, spw_addr + (uint32_t)s * 32u);
            const uint32_t vks = (uint32_t)(s * 16 * AKW) * 4u;   // +16 key rows
#pragma unroll
            for (int ntp = 0; ntp < 4; ntp++) {
                uint32_t bq[4];
                ldsm_x4_trans(bq, svw[b] + boffV[ntp] + vks);
                mma_bf16(oacc[2 * ntp],     af, bq);
                mma_bf16(oacc[2 * ntp + 1], af, bq + 2);
            }
        }
        __syncthreads();   // all warps done with buffer b before refill
        if (kt + 2 < NT) issue(kt + 2, b);
        else CP_COMMIT();
    }

    // ---- Normalize + write O as bf16
    const float iA = 1.f / lA;
    const float iB = 1.f / lB;
    __nv_bfloat16* Og = O + ((size_t)grp * SLEN + qb * 128 + r0) * HEADDIM;
#pragma unroll
    for (int nt = 0; nt < 8; nt++) {
        const int cb = nt * 8 + 2 * t;
        uint32_t wA = pack_bf16x2(oacc[nt][0] * iA, oacc[nt][1] * iA);
        uint32_t wB = pack_bf16x2(oacc[nt][2] * iB, oacc[nt][3] * iB);
        *reinterpret_cast<uint32_t*>(Og + (size_t)gq * HEADDIM + cb) = wA;
        *reinterpret_cast<uint32_t*>(Og + (size_t)(gq + 8) * HEADDIM + cb) = wB;
    }
}

// ---------------------------------------------------------------------------
// Fused residual + LayerNorm (unchanged)
// ---------------------------------------------------------------------------
__global__ __launch_bounds__(256) void ln_kernel(
    const float* __restrict__ x, const float* __restrict__ p,
    const float* __restrict__ gamma, const float* __restrict__ beta,
    float* __restrict__ out)
{
    const int row = blockIdx.x;
    const int t = threadIdx.x;
    const size_t base = (size_t)row * DMODEL + t * 4;

    float4 xv = *(const float4*)(x + base);
    float4 pv = *(const float4*)(p + base);
    float v0 = xv.x + pv.x, v1 = xv.y + pv.y, v2 = xv.z + pv.z, v3 = xv.w + pv.w;

    __shared__ float red[8];
    float s = v0 + v1 + v2 + v3;
#pragma unroll
    for (int off = 16; off >= 1; off >>= 1) s += __shfl_xor_sync(0xffffffffu, s, off);
    if ((t & 31) == 0) red[t >> 5] = s;
    __syncthreads();
    float mu = (red[0] + red[1] + red[2] + red[3] +
                red[4] + red[5] + red[6] + red[7]) * (1.f / DMODEL);
    __syncthreads();

    float d0 = v0 - mu, d1 = v1 - mu, d2 = v2 - mu, d3 = v3 - mu;
    float q = d0 * d0 + d1 * d1 + d2 * d2 + d3 * d3;
#pragma unroll
    for (int off = 16; off >= 1; off >>= 1) q += __shfl_xor_sync(0xffffffffu, q, off);
    if ((t & 31) == 0) red[t >> 5] = q;
    __syncthreads();
    float var = (red[0] + red[1] + red[2] + red[3] +
                 red[4] + red[5] + red[6] + red[7]) * (1.f / DMODEL);
    float rs = rsqrtf(var + 1e-5f);

    float4 gv = *(const float4*)(gamma + t * 4);
    float4 bv = *(const float4*)(beta + t * 4);
    float4 ov;
    ov.x = d0 * rs * gv.x + bv.x;
    ov.y = d1 * rs * gv.y + bv.y;
    ov.z = d2 * rs * gv.z + bv.z;
    ov.w = d3 * rs * gv.w + bv.w;
    *(float4*)(out + base) = ov;
}

// ---------------------------------------------------------------------------
// Launch
// ---------------------------------------------------------------------------
extern "C" void kernel_launch(void* const* d_in, const int* in_sizes, int n_in,
                              void* d_out, int out_size)
{
    (void)in_sizes; (void)n_in; (void)out_size;
    const float* q_in  = (const float*)d_in[0];
    const float* k_in  = (const float*)d_in[1];
    const float* v_in  = (const float*)d_in[2];
    const unsigned char* mask = (const unsigned char*)d_in[3];
    const float* Wq = (const float*)d_in[4];
    const float* Wk = (const float*)d_in[5];
    const float* Wv = (const float*)d_in[6];
    const float* Wo = (const float*)d_in[7];
    const float* bo = (const float*)d_in[8];
    const float* gamma = (const float*)d_in[9];
    const float* beta  = (const float*)d_in[10];
    float* out = (float*)d_out;

    float* pP;
    __nv_bfloat16 *pQb, *pKb, *pVb, *pOb, *pQin, *pKin, *pVin;
    __nv_bfloat16 *pWqT, *pWkT, *pWvT, *pWoT;
    cudaGetSymbolAddress((void**)&pP, g_P);
    cudaGetSymbolAddress((void**)&pQb, g_Qb);
    cudaGetSymbolAddress((void**)&pKb, g_Kb);
    cudaGetSymbolAddress((void**)&pVb, g_Vb);
    cudaGetSymbolAddress((void**)&pOb, g_Ob);
    cudaGetSymbolAddress((void**)&pQin, g_Qin);
    cudaGetSymbolAddress((void**)&pKin, g_Kin);
    cudaGetSymbolAddress((void**)&pVin, g_Vin);
    cudaGetSymbolAddress((void**)&pWqT, g_WqT);
    cudaGetSymbolAddress((void**)&pWkT, g_WkT);
    cudaGetSymbolAddress((void**)&pWvT, g_WvT);
    cudaGetSymbolAddress((void**)&pWoT, g_WoT);

    cudaFuncSetAttribute(gemm_bf16_qkv, cudaFuncAttributeMaxDynamicSharedMemorySize, GEMM_SMEM);
    cudaFuncSetAttribute(gemm_bf16_out, cudaFuncAttributeMaxDynamicSharedMemorySize, GEMM_SMEM);
    cudaFuncSetAttribute(attn_bf16, cudaFuncAttributeMaxDynamicSharedMemorySize, ATT_SMEM);

    // launches 0-3: weight transposes
    dim3 tgrid(DMODEL / 32, DMODEL / 32);
    dim3 tblk(32, 8);
    transpose1024_bf16<<<tgrid, tblk>>>(Wq, pWqT);
    transpose1024_bf16<<<tgrid, tblk>>>(Wk, pWkT);
    transpose1024_bf16<<<tgrid, tblk>>>(Wv, pWvT);
    transpose1024_bf16<<<tgrid, tblk>>>(Wo, pWoT);

    // launch 4: fused input conversion
    dim3 cgrid(NROWS * DMODEL / (256 * 8), 3);
    cvt_bf16_fused<<<cgrid, 256>>>(q_in, k_in, v_in, pQin, pKin, pVin);

    // launch 5: batched Q/K/V projections
    dim3 ggrid3(DMODEL / 128, NROWS / 128, 3);
    gemm_bf16_qkv<<<ggrid3, 256, GEMM_SMEM>>>(
        pQin, pKin, pVin, pWqT, pWkT, pWvT, pQb, pKb, pVb,
        NROWS, DMODEL, DMODEL);

    // launch 6: attention (V row-major; PV B-operand via ldmatrix.trans)
    dim3 agrid(SLEN / 128, NGROUPS);
    attn_bf16<<<agrid, 256, ATT_SMEM>>>(pQb, pKb, pVb, mask, pOb);

    // launch 7: output projection (+bias, fp32 out)
    dim3 ggrid1(DMODEL / 128, NROWS / 128);
    gemm_bf16_out<<<ggrid1, 256, GEMM_SMEM>>>(pOb, pWoT, bo, pP, NROWS, DMODEL, DMODEL);

    // launch 8: residual + LayerNorm
    ln_kernel<<<NROWS, 256>>>(q_in, pP, gamma, beta, out);
}

// round 11
// speedup vs baseline: 1.0909x; 1.0909x over previous
#include <cuda_runtime.h>
#include <cuda_bf16.h>
#include <math.h>
#include <cstdint>

// Problem constants
#define BATCH   2
#define SLEN    2048
#define DMODEL  1024
#define NHEADS  16
#define HEADDIM 64
#define NROWS   (BATCH * SLEN)      // 4096
#define NGROUPS (BATCH * NHEADS)    // 32 reshaped "heads"

// Scratch (allocation-free rule: __device__ globals)
__device__ float g_P[NROWS * DMODEL];
__device__ __nv_bfloat16 g_Qb[NROWS * DMODEL];
__device__ __nv_bfloat16 g_Kb[NROWS * DMODEL];
__device__ __nv_bfloat16 g_Vb[NROWS * DMODEL];
__device__ __nv_bfloat16 g_VTb[NROWS * DMODEL];  // per-group transposed V
__device__ __nv_bfloat16 g_Ob[NROWS * DMODEL];
__device__ __nv_bfloat16 g_Qin[NROWS * DMODEL];
__device__ __nv_bfloat16 g_Kin[NROWS * DMODEL];
__device__ __nv_bfloat16 g_Vin[NROWS * DMODEL];
__device__ __nv_bfloat16 g_WqT[DMODEL * DMODEL];
__device__ __nv_bfloat16 g_WkT[DMODEL * DMODEL];
__device__ __nv_bfloat16 g_WvT[DMODEL * DMODEL];
__device__ __nv_bfloat16 g_WoT[DMODEL * DMODEL];

// ---------------------------------------------------------------------------
// Helpers (sm_80+ only — compute_103 rejects 'a'-gated PTX like tcgen05)
// ---------------------------------------------------------------------------
__device__ __forceinline__ uint32_t smem_u32(const void* p) {
    uint32_t a;
    asm("{ .reg .u64 t; cvta.to.shared.u64 t, %1; cvt.u32.u64 %0, t; }"
        : "=r"(a) : "l"(p));
    return a;
}

__device__ __forceinline__ void cp_async16(uint32_t saddr, const void* gaddr) {
    asm volatile("cp.async.cg.shared.global [%0], [%1], 16;"
                 :: "r"(saddr), "l"(gaddr) : "memory");
}
#define CP_COMMIT() asm volatile("cp.async.commit_group;" ::: "memory")
#define CP_WAIT1()  asm volatile("cp.async.wait_group 1;" ::: "memory")

__device__ __forceinline__ void mma_bf16(float* d, const uint32_t* a, const uint32_t* b) {
    asm volatile(
        "mma.sync.aligned.m16n8k16.row.col.f32.bf16.bf16.f32 "
        "{%0,%1,%2,%3}, {%4,%5,%6,%7}, {%8,%9}, {%0,%1,%2,%3};"
        : "+f"(d[0]), "+f"(d[1]), "+f"(d[2]), "+f"(d[3])
        : "r"(a[0]), "r"(a[1]), "r"(a[2]), "r"(a[3]), "r"(b[0]), "r"(b[1]));
}

__device__ __forceinline__ void ldsm_x4(uint32_t* r, uint32_t saddr) {
    asm volatile("ldmatrix.sync.aligned.m8n8.x4.shared.b16 {%0,%1,%2,%3}, [%4];"
                 : "=r"(r[0]), "=r"(r[1]), "=r"(r[2]), "=r"(r[3]) : "r"(saddr));
}

__device__ __forceinline__ uint32_t pack_bf16x2(float lo, float hi) {
    __nv_bfloat162 h = __floats2bfloat162_rn(lo, hi);
    return *reinterpret_cast<uint32_t*>(&h);
}

// ---------------------------------------------------------------------------
// Fused fp32 -> bf16 conversion of q/k/v inputs (blockIdx.y selects tensor)
// ---------------------------------------------------------------------------
__global__ __launch_bounds__(256) void cvt_bf16_fused(
    const float* __restrict__ x0, const float* __restrict__ x1,
    const float* __restrict__ x2,
    __nv_bfloat16* __restrict__ y0, __nv_bfloat16* __restrict__ y1,
    __nv_bfloat16* __restrict__ y2)
{
    const int z = blockIdx.y;
    const float* x = (z == 0) ? x0 : (z == 1) ? x1 : x2;
    __nv_bfloat16* y = (z == 0) ? y0 : (z == 1) ? y1 : y2;
    const size_t i = ((size_t)blockIdx.x * 256 + threadIdx.x) * 8;
    float4 a = *(const float4*)(x + i);
    float4 b = *(const float4*)(x + i + 4);
    __nv_bfloat162* yp = reinterpret_cast<__nv_bfloat162*>(y + i);
    yp[0] = __floats2bfloat162_rn(a.x, a.y);
    yp[1] = __floats2bfloat162_rn(a.z, a.w);
    yp[2] = __floats2bfloat162_rn(b.x, b.y);
    yp[3] = __floats2bfloat162_rn(b.z, b.w);
}

// ---------------------------------------------------------------------------
// Fused weight transpose (fp32 -> bf16): Wt[n][k] = bf16(W[k][n]).
// blockIdx.z selects which of the 4 weight matrices.
// ---------------------------------------------------------------------------
__global__ __launch_bounds__(256) void transpose1024_bf16_fused(
    const float* __restrict__ W0, const float* __restrict__ W1,
    const float* __restrict__ W2, const float* __restrict__ W3,
    __nv_bfloat16* __restrict__ T0, __nv_bfloat16* __restrict__ T1,
    __nv_bfloat16* __restrict__ T2, __nv_bfloat16* __restrict__ T3)
{
    const int z = blockIdx.z;
    const float* W = (z == 0) ? W0 : (z == 1) ? W1 : (z == 2) ? W2 : W3;
    __nv_bfloat16* Wt = (z == 0) ? T0 : (z == 1) ? T1 : (z == 2) ? T2 : T3;

    __shared__ float t[32][33];
    const int bx = blockIdx.x * 32, by = blockIdx.y * 32;
    const int x = threadIdx.x, y = threadIdx.y;   // 32 x 8
#pragma unroll
    for (int i = 0; i < 32; i += 8)
        t[y + i][x] = W[(size_t)(by + y + i) * DMODEL + bx + x];
    __syncthreads();
#pragma unroll
    for (int i = 0; i < 32; i += 8)
        Wt[(size_t)(bx + y + i) * DMODEL + by + x] = __float2bfloat16_rn(t[x][y + i]);
}

// ---------------------------------------------------------------------------
// V transpose per group (bf16): V[g][s][d] -> VT[g][d][s]
// (restored from R8 — separate coalesced transpose beats ldmatrix.trans,
//  R9/R10 bisect showed LDSM.T cost ~+30us on attention)
// ---------------------------------------------------------------------------
__global__ __launch_bounds__(256) void vtranspose_bf16(
    const __nv_bfloat16* __restrict__ V, __nv_bfloat16* __restrict__ VT)
{
    __shared__ __nv_bfloat16 t[32][34];
    const int g = blockIdx.z;
    const int s0 = blockIdx.x * 32, d0 = blockIdx.y * 32;
    const int x = threadIdx.x, y = threadIdx.y;   // 32 x 8
    const __nv_bfloat16* Vg = V + (size_t)g * SLEN * HEADDIM;
    __nv_bfloat16* VTg = VT + (size_t)g * SLEN * HEADDIM;
#pragma unroll
    for (int i = 0; i < 32; i += 8)
        t[y + i][x] = Vg[(size_t)(s0 + y + i) * HEADDIM + d0 + x];
    __syncthreads();
#pragma unroll
    for (int i = 0; i < 32; i += 8)
        VTg[(size_t)(d0 + y + i) * SLEN + s0 + x] = t[x][y + i];
}

// ---------------------------------------------------------------------------
// HMMA bf16 GEMM (R8-validated): CTA 128x128, BK=64, 8 warps (4x2),
// warp 32x64, 2-stage cp.async, ldmatrix fragments. Smem 73728 B.
// ---------------------------------------------------------------------------
#define KSW 36
#define TILE_WORDS (128 * KSW)
#define GEMM_SMEM (4 * TILE_WORDS * 4)   // 73728 B

__global__ __launch_bounds__(256) void gemm_bf16_qkv(
    const __nv_bfloat16* __restrict__ A0, const __nv_bfloat16* __restrict__ A1,
    const __nv_bfloat16* __restrict__ A2,
    const __nv_bfloat16* __restrict__ B0, const __nv_bfloat16* __restrict__ B1,
    const __nv_bfloat16* __restrict__ B2,
    __nv_bfloat16* __restrict__ C0, __nv_bfloat16* __restrict__ C1,
    __nv_bfloat16* __restrict__ C2, int M, int N, int K)
{
    extern __shared__ uint32_t shw[];
    uint32_t* sA[2] = { shw,              shw + 2 * TILE_WORDS };
    uint32_t* sB[2] = { shw + TILE_WORDS, shw + 3 * TILE_WORDS };

    const int z = blockIdx.z;
    const __nv_bfloat16* A = (z == 0) ? A0 : (z == 1) ? A1 : A2;
    const __nv_bfloat16* Bt = (z == 0) ? B0 : (z == 1) ? B1 : B2;
    __nv_bfloat16* C = (z == 0) ? C0 : (z == 1) ? C1 : C2;

    const int tid = threadIdx.x;
    const int wid = tid >> 5;
    const int lane = tid & 31;
    const int mb = (wid & 3) * 32;
    const int nb = (wid >> 2) * 64;
    const int g = lane >> 2;
    const int t = lane & 3;
    const int m0 = blockIdx.y * 128;
    const int n0 = blockIdx.x * 128;

    const int quad = lane >> 3;
    const int within = lane & 7;
    const int arow = (quad & 1) * 8 + within;
    const int acol = (quad >> 1) * 4;
    const int brow = (quad >> 1) * 8 + within;
    const int bcol = (quad & 1) * 4;

    const uint32_t aoff0 = (uint32_t)((mb + arow) * KSW + acol) * 4u;
    const uint32_t aoff1 = (uint32_t)((mb + 16 + arow) * KSW + acol) * 4u;
    uint32_t boff[4];
#pragma unroll
    for (int ntp = 0; ntp < 4; ntp++)
        boff[ntp] = (uint32_t)((nb + ntp * 16 + brow) * KSW + bcol) * 4u;

    const uint32_t saw[2] = { smem_u32(sA[0]), smem_u32(sA[1]) };
    const uint32_t sbw[2] = { smem_u32(sB[0]), smem_u32(sB[1]) };

    float acc[2][8][4];
#pragma unroll
    for (int i = 0; i < 2; i++)
#pragma unroll
        for (int j = 0; j < 8; j++)
#pragma unroll
            for (int q = 0; q < 4; q++) acc[i][j][q] = 0.f;

    const int NCH = K / 64;

    auto issue = [&](int c, int b) {
        const __nv_bfloat16* Ag = A + (size_t)m0 * K + (size_t)c * 64;
        const __nv_bfloat16* Bg = Bt + (size_t)n0 * K + (size_t)c * 64;
#pragma unroll
        for (int i = 0; i < 4; i++) {
            const int u = tid + 256 * i;
            const int row = u >> 3;
            const int seg = u & 7;
            const uint32_t so = (uint32_t)(row * KSW + seg * 4) * 4u;
            cp_async16(saw[b] + so, Ag + (size_t)row * K + seg * 8);
            cp_async16(sbw[b] + so, Bg + (size_t)row * K + seg * 8);
        }
        CP_COMMIT();
    };

    issue(0, 0);
    issue(1, 1);

    for (int c = 0; c < NCH; c++) {
        const int b = c & 1;
        CP_WAIT1();
        __syncthreads();
#pragma unroll
        for (int s = 0; s < 4; s++) {
            const uint32_t ks = (uint32_t)s * 32u;
            uint32_t af0[4], af1[4];
            ldsm_x4(af0, saw[b] + aoff0 + ks);
            ldsm_x4(af1, saw[b] + aoff1 + ks);
#pragma unroll
            for (int ntp = 0; ntp < 4; ntp++) {
                uint32_t bq[4];
                ldsm_x4(bq, sbw[b] + boff[ntp] + ks);
                mma_bf16(acc[0][2 * ntp],     af0, bq);
                mma_bf16(acc[1][2 * ntp],     af1, bq);
                mma_bf16(acc[0][2 * ntp + 1], af0, bq + 2);
                mma_bf16(acc[1][2 * ntp + 1], af1, bq + 2);
            }
        }
        __syncthreads();
        if (c + 2 < NCH) issue(c + 2, b);
        else CP_COMMIT();
    }

#pragma unroll
    for (int mt = 0; mt < 2; mt++) {
        const int r = m0 + mb + mt * 16 + g;
#pragma unroll
        for (int nt = 0; nt < 8; nt++) {
            const int cx = n0 + nb + nt * 8 + 2 * t;
            uint32_t w0 = pack_bf16x2(acc[mt][nt][0], acc[mt][nt][1]);
            uint32_t w1 = pack_bf16x2(acc[mt][nt][2], acc[mt][nt][3]);
            *reinterpret_cast<uint32_t*>(C + (size_t)r * N + cx) = w0;
            *reinterpret_cast<uint32_t*>(C + (size_t)(r + 8) * N + cx) = w1;
        }
    }
}

__global__ __launch_bounds__(256) void gemm_bf16_out(
    const __nv_bfloat16* __restrict__ A, const __nv_bfloat16* __restrict__ Bt,
    const float* __restrict__ bias, float* __restrict__ C,
    int M, int N, int K)
{
    extern __shared__ uint32_t shw[];
    uint32_t* sA[2] = { shw,              shw + 2 * TILE_WORDS };
    uint32_t* sB[2] = { shw + TILE_WORDS, shw + 3 * TILE_WORDS };

    const int tid = threadIdx.x;
    const int wid = tid >> 5;
    const int lane = tid & 31;
    const int mb = (wid & 3) * 32;
    const int nb = (wid >> 2) * 64;
    const int g = lane >> 2;
    const int t = lane & 3;
    const int m0 = blockIdx.y * 128;
    const int n0 = blockIdx.x * 128;

    const int quad = lane >> 3;
    const int within = lane & 7;
    const int arow = (quad & 1) * 8 + within;
    const int acol = (quad >> 1) * 4;
    const int brow = (quad >> 1) * 8 + within;
    const int bcol = (quad & 1) * 4;

    const uint32_t aoff0 = (uint32_t)((mb + arow) * KSW + acol) * 4u;
    const uint32_t aoff1 = (uint32_t)((mb + 16 + arow) * KSW + acol) * 4u;
    uint32_t boff[4];
#pragma unroll
    for (int ntp = 0; ntp < 4; ntp++)
        boff[ntp] = (uint32_t)((nb + ntp * 16 + brow) * KSW + bcol) * 4u;

    const uint32_t saw[2] = { smem_u32(sA[0]), smem_u32(sA[1]) };
    const uint32_t sbw[2] = { smem_u32(sB[0]), smem_u32(sB[1]) };

    float acc[2][8][4];
#pragma unroll
    for (int i = 0; i < 2; i++)
#pragma unroll
        for (int j = 0; j < 8; j++)
#pragma unroll
            for (int q = 0; q < 4; q++) acc[i][j][q] = 0.f;

    const int NCH = K / 64;

    auto issue = [&](int c, int b) {
        const __nv_bfloat16* Ag = A + (size_t)m0 * K + (size_t)c * 64;
        const __nv_bfloat16* Bg = Bt + (size_t)n0 * K + (size_t)c * 64;
#pragma unroll
        for (int i = 0; i < 4; i++) {
            const int u = tid + 256 * i;
            const int row = u >> 3;
            const int seg = u & 7;
            const uint32_t so = (uint32_t)(row * KSW + seg * 4) * 4u;
            cp_async16(saw[b] + so, Ag + (size_t)row * K + seg * 8);
            cp_async16(sbw[b] + so, Bg + (size_t)row * K + seg * 8);
        }
        CP_COMMIT();
    };

    issue(0, 0);
    issue(1, 1);

    for (int c = 0; c < NCH; c++) {
        const int b = c & 1;
        CP_WAIT1();
        __syncthreads();
#pragma unroll
        for (int s = 0; s < 4; s++) {
            const uint32_t ks = (uint32_t)s * 32u;
            uint32_t af0[4], af1[4];
            ldsm_x4(af0, saw[b] + aoff0 + ks);
            ldsm_x4(af1, saw[b] + aoff1 + ks);
#pragma unroll
            for (int ntp = 0; ntp < 4; ntp++) {
                uint32_t bq[4];
                ldsm_x4(bq, sbw[b] + boff[ntp] + ks);
                mma_bf16(acc[0][2 * ntp],     af0, bq);
                mma_bf16(acc[1][2 * ntp],     af1, bq);
                mma_bf16(acc[0][2 * ntp + 1], af0, bq + 2);
                mma_bf16(acc[1][2 * ntp + 1], af1, bq + 2);
            }
        }
        __syncthreads();
        if (c + 2 < NCH) issue(c + 2, b);
        else CP_COMMIT();
    }

#pragma unroll
    for (int mt = 0; mt < 2; mt++) {
        const int r = m0 + mb + mt * 16 + g;
#pragma unroll
        for (int nt = 0; nt < 8; nt++) {
            const int cx = n0 + nb + nt * 8 + 2 * t;
            const float b0 = __ldg(&bias[cx]);
            const float b1 = __ldg(&bias[cx + 1]);
            float2 v0, v1;
            v0.x = acc[mt][nt][0] + b0; v0.y = acc[mt][nt][1] + b1;
            v1.x = acc[mt][nt][2] + b0; v1.y = acc[mt][nt][3] + b1;
            *(float2*)(C + (size_t)r * N + cx) = v0;
            *(float2*)(C + (size_t)(r + 8) * N + cx) = v1;
        }
    }
}

// ---------------------------------------------------------------------------
// bf16 HMMA flash attention (R8-validated verbatim). Q,K bf16 [32][2048][64];
// VT bf16 [32][64][2048]. CTA: 128 Q rows x 1 group, 8 warps,
// K-tiles of 64 keys, 2-stage cp.async. Smem 55296 B => 4 CTAs/SM.
// ---------------------------------------------------------------------------
#define AKW 36
#define ATT_TILE (64 * AKW)
#define ATT_SMEM ((4 * ATT_TILE + 128 * AKW) * 4)   // 55296 B

__global__ __launch_bounds__(256) void attn_bf16(
    const __nv_bfloat16* __restrict__ Q, const __nv_bfloat16* __restrict__ K,
    const __nv_bfloat16* __restrict__ VT, const unsigned char* __restrict__ mask,
    __nv_bfloat16* __restrict__ O)
{
    extern __shared__ uint32_t smw[];
    uint32_t* sP = smw + 4 * ATT_TILE;   // [128][AKW]

    const int tid = threadIdx.x;
    const int wid = tid >> 5;
    const int lane = tid & 31;
    const int gq = lane >> 2;
    const int t = lane & 3;
    const int qb = blockIdx.x;
    const int grp = blockIdx.y;
    const int r0 = wid * 16;

    const int quad = lane >> 3;
    const int within = lane & 7;
    const int arow = (quad & 1) * 8 + within;
    const int acol = (quad >> 1) * 4;
    const int brow = (quad >> 1) * 8 + within;
    const int bcol = (quad & 1) * 4;

    uint32_t boffA[4];
#pragma unroll
    for (int ntp = 0; ntp < 4; ntp++)
        boffA[ntp] = (uint32_t)((ntp * 16 + brow) * AKW + bcol) * 4u;

    const uint32_t skw[2] = { smem_u32(smw), smem_u32(smw + ATT_TILE) };
    const uint32_t svw[2] = { smem_u32(smw + 2 * ATT_TILE), smem_u32(smw + 3 * ATT_TILE) };

    const __nv_bfloat16* Qg = Q + ((size_t)grp * SLEN + qb * 128 + r0) * HEADDIM;
    const __nv_bfloat16* Kg = K + (size_t)grp * SLEN * HEADDIM;
    const __nv_bfloat16* VTg = VT + (size_t)grp * SLEN * HEADDIM;
    const unsigned char* mrow =
        mask + (size_t)(grp % BATCH) * SLEN * SLEN + (size_t)(qb * 128 + r0) * SLEN;

    auto issue = [&](int kt, int b) {
#pragma unroll
        for (int i = 0; i < 2; i++) {
            const int u = tid + 256 * i;
            const int row = u >> 3;
            const int seg = u & 7;
            const uint32_t so = (uint32_t)(row * AKW + seg * 4) * 4u;
            cp_async16(skw[b] + so, Kg + (size_t)(kt * 64 + row) * HEADDIM + seg * 8);
            cp_async16(svw[b] + so, VTg + (size_t)row * SLEN + kt * 64 + seg * 8);
        }
        CP_COMMIT();
    };

    // ---- Stage Q (warp-private rows of sP), build persistent A fragments
    uint32_t* sQw = sP + r0 * AKW;
    const uint32_t spw_addr = smem_u32(sQw) + (uint32_t)(arow * AKW + acol) * 4u;
    {
        const int row = lane >> 1;
        const int cs = (lane & 1) * 16;
#pragma unroll
        for (int j = 0; j < 4; j++) {
            uint4 v = *(const uint4*)(Qg + (size_t)row * HEADDIM + (cs + j * 4) * 2);
            *(uint4*)&sQw[row * AKW + cs + j * 4] = v;
        }
    }
    __syncwarp();
    uint32_t qf[4][4];
#pragma unroll
    for (int s = 0; s < 4; s++)
        ldsm_x4(qf[s], spw_addr + (uint32_t)s * 32u);
    __syncthreads();   // Q fragments captured before sP reused for P

    issue(0, 0);
    issue(1, 1);

    float oacc[8][4];
#pragma unroll
    for (int nt = 0; nt < 8; nt++)
#pragma unroll
        for (int q = 0; q < 4; q++) oacc[nt][q] = 0.f;
    float mA = -INFINITY, mB = -INFINITY, lA = 0.f, lB = 0.f;

    const float scale = 0.125f;
    uint32_t* sPw = sP + r0 * AKW;
    const int NT = SLEN / 64;

    for (int kt = 0; kt < NT; kt++) {
        const int b = kt & 1;
        CP_WAIT1();
        __syncthreads();

        // ---- S = Q K^T
        float sacc[8][4];
#pragma unroll
        for (int nt = 0; nt < 8; nt++)
#pragma unroll
            for (int q = 0; q < 4; q++) sacc[nt][q] = 0.f;
#pragma unroll
        for (int s = 0; s < 4; s++) {
            const uint32_t ks = (uint32_t)s * 32u;
#pragma unroll
            for (int ntp = 0; ntp < 4; ntp++) {
                uint32_t bq[4];
                ldsm_x4(bq, skw[b] + boffA[ntp] + ks);
                mma_bf16(sacc[2 * ntp],     qf[s], bq);
                mma_bf16(sacc[2 * ntp + 1], qf[s], bq + 2);
            }
        }

        // ---- Mask + scale
#pragma unroll
        for (int nt = 0; nt < 8; nt++) {
            const int cb = kt * 64 + nt * 8 + 2 * t;
            uchar2 ma = *(const uchar2*)(mrow + (size_t)gq * SLEN + cb);
            uchar2 mb2 = *(const uchar2*)(mrow + (size_t)(gq + 8) * SLEN + cb);
            sacc[nt][0] = ma.x ? -1e9f : sacc[nt][0] * scale;
            sacc[nt][1] = ma.y ? -1e9f : sacc[nt][1] * scale;
            sacc[nt][2] = mb2.x ? -1e9f : sacc[nt][2] * scale;
            sacc[nt][3] = mb2.y ? -1e9f : sacc[nt][3] * scale;
        }

        // ---- Online softmax
        float mxA = -INFINITY, mxB = -INFINITY;
#pragma unroll
        for (int nt = 0; nt < 8; nt++) {
            mxA = fmaxf(mxA, fmaxf(sacc[nt][0], sacc[nt][1]));
            mxB = fmaxf(mxB, fmaxf(sacc[nt][2], sacc[nt][3]));
        }
        mxA = fmaxf(mxA, __shfl_xor_sync(0xffffffffu, mxA, 1));
        mxA = fmaxf(mxA, __shfl_xor_sync(0xffffffffu, mxA, 2));
        mxB = fmaxf(mxB, __shfl_xor_sync(0xffffffffu, mxB, 1));
        mxB = fmaxf(mxB, __shfl_xor_sync(0xffffffffu, mxB, 2));

        const float mnA = fmaxf(mA, mxA);
        const float mnB = fmaxf(mB, mxB);
        const float cA = __expf(mA - mnA);
        const float cB = __expf(mB - mnB);
        float suA = 0.f, suB = 0.f;
#pragma unroll
        for (int nt = 0; nt < 8; nt++) {
            sacc[nt][0] = __expf(sacc[nt][0] - mnA);
            sacc[nt][1] = __expf(sacc[nt][1] - mnA);
            sacc[nt][2] = __expf(sacc[nt][2] - mnB);
            sacc[nt][3] = __expf(sacc[nt][3] - mnB);
            suA += sacc[nt][0] + sacc[nt][1];
            suB += sacc[nt][2] + sacc[nt][3];
        }
        suA += __shfl_xor_sync(0xffffffffu, suA, 1);
        suA += __shfl_xor_sync(0xffffffffu, suA, 2);
        suB += __shfl_xor_sync(0xffffffffu, suB, 1);
        suB += __shfl_xor_sync(0xffffffffu, suB, 2);
        lA = lA * cA + suA;
        lB = lB * cB + suB;
        mA = mnA;
        mB = mnB;
#pragma unroll
        for (int nt = 0; nt < 8; nt++) {
            oacc[nt][0] *= cA; oacc[nt][1] *= cA;
            oacc[nt][2] *= cB; oacc[nt][3] *= cB;
        }

        // ---- Stage P packed bf16x2 (warp-private rows)
#pragma unroll
        for (int nt = 0; nt < 8; nt++) {
            sPw[gq * AKW + nt * 4 + t]       = pack_bf16x2(sacc[nt][0], sacc[nt][1]);
            sPw[(gq + 8) * AKW + nt * 4 + t] = pack_bf16x2(sacc[nt][2], sacc[nt][3]);
        }
        __syncwarp();

        // ---- O += P V  (A=P ldmatrix; B=VT ldmatrix non-trans)
#pragma unroll
        for (int s = 0; s < 4; s++) {
            const uint32_t ks = (uint32_t)s * 32u;
            uint32_t af[4];
            ldsm_x4(af, spw_addr + ks);
#pragma unroll
            for (int ntp = 0; ntp < 4; ntp++) {
                uint32_t bq[4];
                ldsm_x4(bq, svw[b] + boffA[ntp] + ks);
                mma_bf16(oacc[2 * ntp],     af, bq);
                mma_bf16(oacc[2 * ntp + 1], af, bq + 2);
            }
        }
        __syncthreads();
        if (kt + 2 < NT) issue(kt + 2, b);
        else CP_COMMIT();
    }

    // ---- Normalize + write O as bf16
    const float iA = 1.f / lA;
    const float iB = 1.f / lB;
    __nv_bfloat16* Og = O + ((size_t)grp * SLEN + qb * 128 + r0) * HEADDIM;
#pragma unroll
    for (int nt = 0; nt < 8; nt++) {
        const int cb = nt * 8 + 2 * t;
        uint32_t wA = pack_bf16x2(oacc[nt][0] * iA, oacc[nt][1] * iA);
        uint32_t wB = pack_bf16x2(oacc[nt][2] * iB, oacc[nt][3] * iB);
        *reinterpret_cast<uint32_t*>(Og + (size_t)gq * HEADDIM + cb) = wA;
        *reinterpret_cast<uint32_t*>(Og + (size_t)(gq + 8) * HEADDIM + cb) = wB;
    }
}

// ---------------------------------------------------------------------------
// Fused residual + LayerNorm (unchanged)
// ---------------------------------------------------------------------------
__global__ __launch_bounds__(256) void ln_kernel(
    const float* __restrict__ x, const float* __restrict__ p,
    const float* __restrict__ gamma, const float* __restrict__ beta,
    float* __restrict__ out)
{
    const int row = blockIdx.x;
    const int t = threadIdx.x;
    const size_t base = (size_t)row * DMODEL + t * 4;

    float4 xv = *(const float4*)(x + base);
    float4 pv = *(const float4*)(p + base);
    float v0 = xv.x + pv.x, v1 = xv.y + pv.y, v2 = xv.z + pv.z, v3 = xv.w + pv.w;

    __shared__ float red[8];
    float s = v0 + v1 + v2 + v3;
#pragma unroll
    for (int off = 16; off >= 1; off >>= 1) s += __shfl_xor_sync(0xffffffffu, s, off);
    if ((t & 31) == 0) red[t >> 5] = s;
    __syncthreads();
    float mu = (red[0] + red[1] + red[2] + red[3] +
                red[4] + red[5] + red[6] + red[7]) * (1.f / DMODEL);
    __syncthreads();

    float d0 = v0 - mu, d1 = v1 - mu, d2 = v2 - mu, d3 = v3 - mu;
    float q = d0 * d0 + d1 * d1 + d2 * d2 + d3 * d3;
#pragma unroll
    for (int off = 16; off >= 1; off >>= 1) q += __shfl_xor_sync(0xffffffffu, q, off);
    if ((t & 31) == 0) red[t >> 5] = q;
    __syncthreads();
    float var = (red[0] + red[1] + red[2] + red[3] +
                 red[4] + red[5] + red[6] + red[7]) * (1.f / DMODEL);
    float rs = rsqrtf(var + 1e-5f);

    float4 gv = *(const float4*)(gamma + t * 4);
    float4 bv = *(const float4*)(beta + t * 4);
    float4 ov;
    ov.x = d0 * rs * gv.x + bv.x;
    ov.y = d1 * rs * gv.y + bv.y;
    ov.z = d2 * rs * gv.z + bv.z;
    ov.w = d3 * rs * gv.w + bv.w;
    *(float4*)(out + base) = ov;
}

// ---------------------------------------------------------------------------
// Launch
// ---------------------------------------------------------------------------
extern "C" void kernel_launch(void* const* d_in, const int* in_sizes, int n_in,
                              void* d_out, int out_size)
{
    (void)in_sizes; (void)n_in; (void)out_size;
    const float* q_in  = (const float*)d_in[0];
    const float* k_in  = (const float*)d_in[1];
    const float* v_in  = (const float*)d_in[2];
    const unsigned char* mask = (const unsigned char*)d_in[3];
    const float* Wq = (const float*)d_in[4];
    const float* Wk = (const float*)d_in[5];
    const float* Wv = (const float*)d_in[6];
    const float* Wo = (const float*)d_in[7];
    const float* bo = (const float*)d_in[8];
    const float* gamma = (const float*)d_in[9];
    const float* beta  = (const float*)d_in[10];
    float* out = (float*)d_out;

    float* pP;
    __nv_bfloat16 *pQb, *pKb, *pVb, *pVTb, *pOb, *pQin, *pKin, *pVin;
    __nv_bfloat16 *pWqT, *pWkT, *pWvT, *pWoT;
    cudaGetSymbolAddress((void**)&pP, g_P);
    cudaGetSymbolAddress((void**)&pQb, g_Qb);
    cudaGetSymbolAddress((void**)&pKb, g_Kb);
    cudaGetSymbolAddress((void**)&pVb, g_Vb);
    cudaGetSymbolAddress((void**)&pVTb, g_VTb);
    cudaGetSymbolAddress((void**)&pOb, g_Ob);
    cudaGetSymbolAddress((void**)&pQin, g_Qin);
    cudaGetSymbolAddress((void**)&pKin, g_Kin);
    cudaGetSymbolAddress((void**)&pVin, g_Vin);
    cudaGetSymbolAddress((void**)&pWqT, g_WqT);
    cudaGetSymbolAddress((void**)&pWkT, g_WkT);
    cudaGetSymbolAddress((void**)&pWvT, g_WvT);
    cudaGetSymbolAddress((void**)&pWoT, g_WoT);

    cudaFuncSetAttribute(gemm_bf16_qkv, cudaFuncAttributeMaxDynamicSharedMemorySize, GEMM_SMEM);
    cudaFuncSetAttribute(gemm_bf16_out, cudaFuncAttributeMaxDynamicSharedMemorySize, GEMM_SMEM);
    cudaFuncSetAttribute(attn_bf16, cudaFuncAttributeMaxDynamicSharedMemorySize, ATT_SMEM);

    // launch 0: fused weight transposes (z selects matrix)
    dim3 tgrid(DMODEL / 32, DMODEL / 32, 4);
    dim3 tblk(32, 8);
    transpose1024_bf16_fused<<<tgrid, tblk>>>(Wq, Wk, Wv, Wo, pWqT, pWkT, pWvT, pWoT);

    // launch 1: fused input conversion
    dim3 cgrid(NROWS * DMODEL / (256 * 8), 3);
    cvt_bf16_fused<<<cgrid, 256>>>(q_in, k_in, v_in, pQin, pKin, pVin);

    // launch 2: batched Q/K/V projections
    dim3 ggrid3(DMODEL / 128, NROWS / 128, 3);
    gemm_bf16_qkv<<<ggrid3, 256, GEMM_SMEM>>>(
        pQin, pKin, pVin, pWqT, pWkT, pWvT, pQb, pKb, pVb,
        NROWS, DMODEL, DMODEL);

    // launch 3: V -> VT per group
    dim3 vgrid(SLEN / 32, HEADDIM / 32, NGROUPS);
    vtranspose_bf16<<<vgrid, tblk>>>(pVb, pVTb);

    // launch 4: attention
    dim3 agrid(SLEN / 128, NGROUPS);
    attn_bf16<<<agrid, 256, ATT_SMEM>>>(pQb, pKb, pVTb, mask, pOb);

    // launch 5: output projection (+bias, fp32 out)
    dim3 ggrid1(DMODEL / 128, NROWS / 128);
    gemm_bf16_out<<<ggrid1, 256, GEMM_SMEM>>>(pOb, pWoT, bo, pP, NROWS, DMODEL, DMODEL);

    // launch 6: residual + LayerNorm
    ln_kernel<<<NROWS, 256>>>(q_in, pP, gamma, beta, out);
}

// round 12
// speedup vs baseline: 1.1307x; 1.0364x over previous
#include <cuda_runtime.h>
#include <cuda_bf16.h>
#include <math.h>
#include <cstdint>

// Problem constants
#define BATCH   2
#define SLEN    2048
#define DMODEL  1024
#define NHEADS  16
#define HEADDIM 64
#define NROWS   (BATCH * SLEN)      // 4096
#define NGROUPS (BATCH * NHEADS)    // 32 reshaped "heads"

// Scratch (allocation-free rule: __device__ globals)
__device__ float g_P[NROWS * DMODEL];
__device__ __nv_bfloat16 g_Qb[NROWS * DMODEL];
__device__ __nv_bfloat16 g_Kb[NROWS * DMODEL];
__device__ __nv_bfloat16 g_Vb[NROWS * DMODEL];
__device__ __nv_bfloat16 g_VTb[NROWS * DMODEL];  // per-group transposed V
__device__ __nv_bfloat16 g_Ob[NROWS * DMODEL];
__device__ __nv_bfloat16 g_Qin[NROWS * DMODEL];
__device__ __nv_bfloat16 g_Kin[NROWS * DMODEL];
__device__ __nv_bfloat16 g_Vin[NROWS * DMODEL];
__device__ __nv_bfloat16 g_WqT[DMODEL * DMODEL];
__device__ __nv_bfloat16 g_WkT[DMODEL * DMODEL];
__device__ __nv_bfloat16 g_WvT[DMODEL * DMODEL];
__device__ __nv_bfloat16 g_WoT[DMODEL * DMODEL];

// ---------------------------------------------------------------------------
// Helpers (sm_80+ only — compute_103 rejects 'a'-gated PTX like tcgen05)
// ---------------------------------------------------------------------------
__device__ __forceinline__ uint32_t smem_u32(const void* p) {
    uint32_t a;
    asm("{ .reg .u64 t; cvta.to.shared.u64 t, %1; cvt.u32.u64 %0, t; }"
        : "=r"(a) : "l"(p));
    return a;
}

__device__ __forceinline__ void cp_async16(uint32_t saddr, const void* gaddr) {
    asm volatile("cp.async.cg.shared.global [%0], [%1], 16;"
                 :: "r"(saddr), "l"(gaddr) : "memory");
}
#define CP_COMMIT() asm volatile("cp.async.commit_group;" ::: "memory")
#define CP_WAIT1()  asm volatile("cp.async.wait_group 1;" ::: "memory")

__device__ __forceinline__ void mma_bf16(float* d, const uint32_t* a, const uint32_t* b) {
    asm volatile(
        "mma.sync.aligned.m16n8k16.row.col.f32.bf16.bf16.f32 "
        "{%0,%1,%2,%3}, {%4,%5,%6,%7}, {%8,%9}, {%0,%1,%2,%3};"
        : "+f"(d[0]), "+f"(d[1]), "+f"(d[2]), "+f"(d[3])
        : "r"(a[0]), "r"(a[1]), "r"(a[2]), "r"(a[3]), "r"(b[0]), "r"(b[1]));
}

__device__ __forceinline__ void ldsm_x4(uint32_t* r, uint32_t saddr) {
    asm volatile("ldmatrix.sync.aligned.m8n8.x4.shared.b16 {%0,%1,%2,%3}, [%4];"
                 : "=r"(r[0]), "=r"(r[1]), "=r"(r[2]), "=r"(r[3]) : "r"(saddr));
}

__device__ __forceinline__ uint32_t pack_bf16x2(float lo, float hi) {
    __nv_bfloat162 h = __floats2bfloat162_rn(lo, hi);
    return *reinterpret_cast<uint32_t*>(&h);
}

// ---------------------------------------------------------------------------
// Fused fp32 -> bf16 conversion of q/k/v inputs (blockIdx.y selects tensor)
// ---------------------------------------------------------------------------
__global__ __launch_bounds__(256) void cvt_bf16_fused(
    const float* __restrict__ x0, const float* __restrict__ x1,
    const float* __restrict__ x2,
    __nv_bfloat16* __restrict__ y0, __nv_bfloat16* __restrict__ y1,
    __nv_bfloat16* __restrict__ y2)
{
    const int z = blockIdx.y;
    const float* x = (z == 0) ? x0 : (z == 1) ? x1 : x2;
    __nv_bfloat16* y = (z == 0) ? y0 : (z == 1) ? y1 : y2;
    const size_t i = ((size_t)blockIdx.x * 256 + threadIdx.x) * 8;
    float4 a = *(const float4*)(x + i);
    float4 b = *(const float4*)(x + i + 4);
    __nv_bfloat162* yp = reinterpret_cast<__nv_bfloat162*>(y + i);
    yp[0] = __floats2bfloat162_rn(a.x, a.y);
    yp[1] = __floats2bfloat162_rn(a.z, a.w);
    yp[2] = __floats2bfloat162_rn(b.x, b.y);
    yp[3] = __floats2bfloat162_rn(b.z, b.w);
}

// ---------------------------------------------------------------------------
// Fused weight transpose (fp32 -> bf16): Wt[n][k] = bf16(W[k][n]).
// blockIdx.z selects which of the 4 weight matrices.
// ---------------------------------------------------------------------------
__global__ __launch_bounds__(256) void transpose1024_bf16_fused(
    const float* __restrict__ W0, const float* __restrict__ W1,
    const float* __restrict__ W2, const float* __restrict__ W3,
    __nv_bfloat16* __restrict__ T0, __nv_bfloat16* __restrict__ T1,
    __nv_bfloat16* __restrict__ T2, __nv_bfloat16* __restrict__ T3)
{
    const int z = blockIdx.z;
    const float* W = (z == 0) ? W0 : (z == 1) ? W1 : (z == 2) ? W2 : W3;
    __nv_bfloat16* Wt = (z == 0) ? T0 : (z == 1) ? T1 : (z == 2) ? T2 : T3;

    __shared__ float t[32][33];
    const int bx = blockIdx.x * 32, by = blockIdx.y * 32;
    const int x = threadIdx.x, y = threadIdx.y;   // 32 x 8
#pragma unroll
    for (int i = 0; i < 32; i += 8)
        t[y + i][x] = W[(size_t)(by + y + i) * DMODEL + bx + x];
    __syncthreads();
#pragma unroll
    for (int i = 0; i < 32; i += 8)
        Wt[(size_t)(bx + y + i) * DMODEL + by + x] = __float2bfloat16_rn(t[x][y + i]);
}

// ---------------------------------------------------------------------------
// V transpose per group (bf16): V[g][s][d] -> VT[g][d][s]
// ---------------------------------------------------------------------------
__global__ __launch_bounds__(256) void vtranspose_bf16(
    const __nv_bfloat16* __restrict__ V, __nv_bfloat16* __restrict__ VT)
{
    __shared__ __nv_bfloat16 t[32][34];
    const int g = blockIdx.z;
    const int s0 = blockIdx.x * 32, d0 = blockIdx.y * 32;
    const int x = threadIdx.x, y = threadIdx.y;   // 32 x 8
    const __nv_bfloat16* Vg = V + (size_t)g * SLEN * HEADDIM;
    __nv_bfloat16* VTg = VT + (size_t)g * SLEN * HEADDIM;
#pragma unroll
    for (int i = 0; i < 32; i += 8)
        t[y + i][x] = Vg[(size_t)(s0 + y + i) * HEADDIM + d0 + x];
    __syncthreads();
#pragma unroll
    for (int i = 0; i < 32; i += 8)
        VTg[(size_t)(d0 + y + i) * SLEN + s0 + x] = t[x][y + i];
}

// ---------------------------------------------------------------------------
// HMMA bf16 GEMM (R8-validated): CTA 128x128, BK=64, 8 warps (4x2),
// warp 32x64, 2-stage cp.async, ldmatrix fragments. Smem 73728 B.
// ---------------------------------------------------------------------------
#define KSW 36
#define TILE_WORDS (128 * KSW)
#define GEMM_SMEM (4 * TILE_WORDS * 4)   // 73728 B

__global__ __launch_bounds__(256) void gemm_bf16_qkv(
    const __nv_bfloat16* __restrict__ A0, const __nv_bfloat16* __restrict__ A1,
    const __nv_bfloat16* __restrict__ A2,
    const __nv_bfloat16* __restrict__ B0, const __nv_bfloat16* __restrict__ B1,
    const __nv_bfloat16* __restrict__ B2,
    __nv_bfloat16* __restrict__ C0, __nv_bfloat16* __restrict__ C1,
    __nv_bfloat16* __restrict__ C2, int M, int N, int K)
{
    extern __shared__ uint32_t shw[];
    uint32_t* sA[2] = { shw,              shw + 2 * TILE_WORDS };
    uint32_t* sB[2] = { shw + TILE_WORDS, shw + 3 * TILE_WORDS };

    const int z = blockIdx.z;
    const __nv_bfloat16* A = (z == 0) ? A0 : (z == 1) ? A1 : A2;
    const __nv_bfloat16* Bt = (z == 0) ? B0 : (z == 1) ? B1 : B2;
    __nv_bfloat16* C = (z == 0) ? C0 : (z == 1) ? C1 : C2;

    const int tid = threadIdx.x;
    const int wid = tid >> 5;
    const int lane = tid & 31;
    const int mb = (wid & 3) * 32;
    const int nb = (wid >> 2) * 64;
    const int g = lane >> 2;
    const int t = lane & 3;
    const int m0 = blockIdx.y * 128;
    const int n0 = blockIdx.x * 128;

    const int quad = lane >> 3;
    const int within = lane & 7;
    const int arow = (quad & 1) * 8 + within;
    const int acol = (quad >> 1) * 4;
    const int brow = (quad >> 1) * 8 + within;
    const int bcol = (quad & 1) * 4;

    const uint32_t aoff0 = (uint32_t)((mb + arow) * KSW + acol) * 4u;
    const uint32_t aoff1 = (uint32_t)((mb + 16 + arow) * KSW + acol) * 4u;
    uint32_t boff[4];
#pragma unroll
    for (int ntp = 0; ntp < 4; ntp++)
        boff[ntp] = (uint32_t)((nb + ntp * 16 + brow) * KSW + bcol) * 4u;

    const uint32_t saw[2] = { smem_u32(sA[0]), smem_u32(sA[1]) };
    const uint32_t sbw[2] = { smem_u32(sB[0]), smem_u32(sB[1]) };

    float acc[2][8][4];
#pragma unroll
    for (int i = 0; i < 2; i++)
#pragma unroll
        for (int j = 0; j < 8; j++)
#pragma unroll
            for (int q = 0; q < 4; q++) acc[i][j][q] = 0.f;

    const int NCH = K / 64;

    auto issue = [&](int c, int b) {
        const __nv_bfloat16* Ag = A + (size_t)m0 * K + (size_t)c * 64;
        const __nv_bfloat16* Bg = Bt + (size_t)n0 * K + (size_t)c * 64;
#pragma unroll
        for (int i = 0; i < 4; i++) {
            const int u = tid + 256 * i;
            const int row = u >> 3;
            const int seg = u & 7;
            const uint32_t so = (uint32_t)(row * KSW + seg * 4) * 4u;
            cp_async16(saw[b] + so, Ag + (size_t)row * K + seg * 8);
            cp_async16(sbw[b] + so, Bg + (size_t)row * K + seg * 8);
        }
        CP_COMMIT();
    };

    issue(0, 0);
    issue(1, 1);

    for (int c = 0; c < NCH; c++) {
        const int b = c & 1;
        CP_WAIT1();
        __syncthreads();
#pragma unroll
        for (int s = 0; s < 4; s++) {
            const uint32_t ks = (uint32_t)s * 32u;
            uint32_t af0[4], af1[4];
            ldsm_x4(af0, saw[b] + aoff0 + ks);
            ldsm_x4(af1, saw[b] + aoff1 + ks);
#pragma unroll
            for (int ntp = 0; ntp < 4; ntp++) {
                uint32_t bq[4];
                ldsm_x4(bq, sbw[b] + boff[ntp] + ks);
                mma_bf16(acc[0][2 * ntp],     af0, bq);
                mma_bf16(acc[1][2 * ntp],     af1, bq);
                mma_bf16(acc[0][2 * ntp + 1], af0, bq + 2);
                mma_bf16(acc[1][2 * ntp + 1], af1, bq + 2);
            }
        }
        __syncthreads();
        if (c + 2 < NCH) issue(c + 2, b);
        else CP_COMMIT();
    }

#pragma unroll
    for (int mt = 0; mt < 2; mt++) {
        const int r = m0 + mb + mt * 16 + g;
#pragma unroll
        for (int nt = 0; nt < 8; nt++) {
            const int cx = n0 + nb + nt * 8 + 2 * t;
            uint32_t w0 = pack_bf16x2(acc[mt][nt][0], acc[mt][nt][1]);
            uint32_t w1 = pack_bf16x2(acc[mt][nt][2], acc[mt][nt][3]);
            *reinterpret_cast<uint32_t*>(C + (size_t)r * N + cx) = w0;
            *reinterpret_cast<uint32_t*>(C + (size_t)(r + 8) * N + cx) = w1;
        }
    }
}

__global__ __launch_bounds__(256) void gemm_bf16_out(
    const __nv_bfloat16* __restrict__ A, const __nv_bfloat16* __restrict__ Bt,
    const float* __restrict__ bias, float* __restrict__ C,
    int M, int N, int K)
{
    extern __shared__ uint32_t shw[];
    uint32_t* sA[2] = { shw,              shw + 2 * TILE_WORDS };
    uint32_t* sB[2] = { shw + TILE_WORDS, shw + 3 * TILE_WORDS };

    const int tid = threadIdx.x;
    const int wid = tid >> 5;
    const int lane = tid & 31;
    const int mb = (wid & 3) * 32;
    const int nb = (wid >> 2) * 64;
    const int g = lane >> 2;
    const int t = lane & 3;
    const int m0 = blockIdx.y * 128;
    const int n0 = blockIdx.x * 128;

    const int quad = lane >> 3;
    const int within = lane & 7;
    const int arow = (quad & 1) * 8 + within;
    const int acol = (quad >> 1) * 4;
    const int brow = (quad >> 1) * 8 + within;
    const int bcol = (quad & 1) * 4;

    const uint32_t aoff0 = (uint32_t)((mb + arow) * KSW + acol) * 4u;
    const uint32_t aoff1 = (uint32_t)((mb + 16 + arow) * KSW + acol) * 4u;
    uint32_t boff[4];
#pragma unroll
    for (int ntp = 0; ntp < 4; ntp++)
        boff[ntp] = (uint32_t)((nb + ntp * 16 + brow) * KSW + bcol) * 4u;

    const uint32_t saw[2] = { smem_u32(sA[0]), smem_u32(sA[1]) };
    const uint32_t sbw[2] = { smem_u32(sB[0]), smem_u32(sB[1]) };

    float acc[2][8][4];
#pragma unroll
    for (int i = 0; i < 2; i++)
#pragma unroll
        for (int j = 0; j < 8; j++)
#pragma unroll
            for (int q = 0; q < 4; q++) acc[i][j][q] = 0.f;

    const int NCH = K / 64;

    auto issue = [&](int c, int b) {
        const __nv_bfloat16* Ag = A + (size_t)m0 * K + (size_t)c * 64;
        const __nv_bfloat16* Bg = Bt + (size_t)n0 * K + (size_t)c * 64;
#pragma unroll
        for (int i = 0; i < 4; i++) {
            const int u = tid + 256 * i;
            const int row = u >> 3;
            const int seg = u & 7;
            const uint32_t so = (uint32_t)(row * KSW + seg * 4) * 4u;
            cp_async16(saw[b] + so, Ag + (size_t)row * K + seg * 8);
            cp_async16(sbw[b] + so, Bg + (size_t)row * K + seg * 8);
        }
        CP_COMMIT();
    };

    issue(0, 0);
    issue(1, 1);

    for (int c = 0; c < NCH; c++) {
        const int b = c & 1;
        CP_WAIT1();
        __syncthreads();
#pragma unroll
        for (int s = 0; s < 4; s++) {
            const uint32_t ks = (uint32_t)s * 32u;
            uint32_t af0[4], af1[4];
            ldsm_x4(af0, saw[b] + aoff0 + ks);
            ldsm_x4(af1, saw[b] + aoff1 + ks);
#pragma unroll
            for (int ntp = 0; ntp < 4; ntp++) {
                uint32_t bq[4];
                ldsm_x4(bq, sbw[b] + boff[ntp] + ks);
                mma_bf16(acc[0][2 * ntp],     af0, bq);
                mma_bf16(acc[1][2 * ntp],     af1, bq);
                mma_bf16(acc[0][2 * ntp + 1], af0, bq + 2);
                mma_bf16(acc[1][2 * ntp + 1], af1, bq + 2);
            }
        }
        __syncthreads();
        if (c + 2 < NCH) issue(c + 2, b);
        else CP_COMMIT();
    }

#pragma unroll
    for (int mt = 0; mt < 2; mt++) {
        const int r = m0 + mb + mt * 16 + g;
#pragma unroll
        for (int nt = 0; nt < 8; nt++) {
            const int cx = n0 + nb + nt * 8 + 2 * t;
            const float b0 = __ldg(&bias[cx]);
            const float b1 = __ldg(&bias[cx + 1]);
            float2 v0, v1;
            v0.x = acc[mt][nt][0] + b0; v0.y = acc[mt][nt][1] + b1;
            v1.x = acc[mt][nt][2] + b0; v1.y = acc[mt][nt][3] + b1;
            *(float2*)(C + (size_t)r * N + cx) = v0;
            *(float2*)(C + (size_t)(r + 8) * N + cx) = v1;
        }
    }
}

// ---------------------------------------------------------------------------
// bf16 HMMA flash attention. Q,K bf16 [32][2048][64]; VT bf16 [32][64][2048].
// CTA: 128 Q rows x 1 group, 8 warps, K-tiles of 64 keys, 2-stage cp.async.
// R12: P never touches smem — the mma C-layout of the scores IS the A-fragment
// layout for PV (af = packed sacc pairs), so the sP buffer, 16 STS + 4 LDSM +
// syncwarp per tile are all deleted. Q is staged through the tile buffers
// before the pipeline starts. Smem 36864 B.
// ---------------------------------------------------------------------------
#define AKW 36
#define ATT_TILE (64 * AKW)
#define ATT_SMEM (4 * ATT_TILE * 4)   // 36864 B

__global__ __launch_bounds__(256) void attn_bf16(
    const __nv_bfloat16* __restrict__ Q, const __nv_bfloat16* __restrict__ K,
    const __nv_bfloat16* __restrict__ VT, const unsigned char* __restrict__ mask,
    __nv_bfloat16* __restrict__ O)
{
    extern __shared__ uint32_t smw[];

    const int tid = threadIdx.x;
    const int wid = tid >> 5;
    const int lane = tid & 31;
    const int gq = lane >> 2;
    const int t = lane & 3;
    const int qb = blockIdx.x;
    const int grp = blockIdx.y;
    const int r0 = wid * 16;

    const int quad = lane >> 3;
    const int within = lane & 7;
    const int arow = (quad & 1) * 8 + within;
    const int acol = (quad >> 1) * 4;
    const int brow = (quad >> 1) * 8 + within;
    const int bcol = (quad & 1) * 4;

    uint32_t boffA[4];
#pragma unroll
    for (int ntp = 0; ntp < 4; ntp++)
        boffA[ntp] = (uint32_t)((ntp * 16 + brow) * AKW + bcol) * 4u;

    const uint32_t skw[2] = { smem_u32(smw), smem_u32(smw + ATT_TILE) };
    const uint32_t svw[2] = { smem_u32(smw + 2 * ATT_TILE), smem_u32(smw + 3 * ATT_TILE) };

    const __nv_bfloat16* Qg = Q + ((size_t)grp * SLEN + qb * 128 + r0) * HEADDIM;
    const __nv_bfloat16* Kg = K + (size_t)grp * SLEN * HEADDIM;
    const __nv_bfloat16* VTg = VT + (size_t)grp * SLEN * HEADDIM;
    const unsigned char* mrow =
        mask + (size_t)(grp % BATCH) * SLEN * SLEN + (size_t)(qb * 128 + r0) * SLEN;

    auto issue = [&](int kt, int b) {
#pragma unroll
        for (int i = 0; i < 2; i++) {
            const int u = tid + 256 * i;
            const int row = u >> 3;
            const int seg = u & 7;
            const uint32_t so = (uint32_t)(row * AKW + seg * 4) * 4u;
            cp_async16(skw[b] + so, Kg + (size_t)(kt * 64 + row) * HEADDIM + seg * 8);
            cp_async16(svw[b] + so, VTg + (size_t)row * SLEN + kt * 64 + seg * 8);
        }
        CP_COMMIT();
    };

    // ---- Stage Q through the tile-buffer region (warp-private 16 rows),
    //      build persistent A fragments, then release the region to the pipe.
    uint32_t* sQw = smw + r0 * AKW;   // 128 rows * 144 B = 18432 B < 36864 B
    const uint32_t sq_addr = smem_u32(sQw) + (uint32_t)(arow * AKW + acol) * 4u;
    {
        const int row = lane >> 1;
        const int cs = (lane & 1) * 16;
#pragma unroll
        for (int j = 0; j < 4; j++) {
            uint4 v = *(const uint4*)(Qg + (size_t)row * HEADDIM + (cs + j * 4) * 2);
            *(uint4*)&sQw[row * AKW + cs + j * 4] = v;
        }
    }
    __syncwarp();
    uint32_t qf[4][4];
#pragma unroll
    for (int s = 0; s < 4; s++)
        ldsm_x4(qf[s], sq_addr + (uint32_t)s * 32u);
    __syncthreads();   // Q fragments captured before buffers reused by cp.async

    issue(0, 0);
    issue(1, 1);

    float oacc[8][4];
#pragma unroll
    for (int nt = 0; nt < 8; nt++)
#pragma unroll
        for (int q = 0; q < 4; q++) oacc[nt][q] = 0.f;
    float mA = -INFINITY, mB = -INFINITY, lA = 0.f, lB = 0.f;

    const float scale = 0.125f;
    const int NT = SLEN / 64;

    for (int kt = 0; kt < NT; kt++) {
        const int b = kt & 1;
        CP_WAIT1();
        __syncthreads();

        // ---- S = Q K^T
        float sacc[8][4];
#pragma unroll
        for (int nt = 0; nt < 8; nt++)
#pragma unroll
            for (int q = 0; q < 4; q++) sacc[nt][q] = 0.f;
#pragma unroll
        for (int s = 0; s < 4; s++) {
            const uint32_t ks = (uint32_t)s * 32u;
#pragma unroll
            for (int ntp = 0; ntp < 4; ntp++) {
                uint32_t bq[4];
                ldsm_x4(bq, skw[b] + boffA[ntp] + ks);
                mma_bf16(sacc[2 * ntp],     qf[s], bq);
                mma_bf16(sacc[2 * ntp + 1], qf[s], bq + 2);
            }
        }

        // ---- Mask + scale
#pragma unroll
        for (int nt = 0; nt < 8; nt++) {
            const int cb = kt * 64 + nt * 8 + 2 * t;
            uchar2 ma = *(const uchar2*)(mrow + (size_t)gq * SLEN + cb);
            uchar2 mb2 = *(const uchar2*)(mrow + (size_t)(gq + 8) * SLEN + cb);
            sacc[nt][0] = ma.x ? -1e9f : sacc[nt][0] * scale;
            sacc[nt][1] = ma.y ? -1e9f : sacc[nt][1] * scale;
            sacc[nt][2] = mb2.x ? -1e9f : sacc[nt][2] * scale;
            sacc[nt][3] = mb2.y ? -1e9f : sacc[nt][3] * scale;
        }

        // ---- Online softmax
        float mxA = -INFINITY, mxB = -INFINITY;
#pragma unroll
        for (int nt = 0; nt < 8; nt++) {
            mxA = fmaxf(mxA, fmaxf(sacc[nt][0], sacc[nt][1]));
            mxB = fmaxf(mxB, fmaxf(sacc[nt][2], sacc[nt][3]));
        }
        mxA = fmaxf(mxA, __shfl_xor_sync(0xffffffffu, mxA, 1));
        mxA = fmaxf(mxA, __shfl_xor_sync(0xffffffffu, mxA, 2));
        mxB = fmaxf(mxB, __shfl_xor_sync(0xffffffffu, mxB, 1));
        mxB = fmaxf(mxB, __shfl_xor_sync(0xffffffffu, mxB, 2));

        const float mnA = fmaxf(mA, mxA);
        const float mnB = fmaxf(mB, mxB);
        const float cA = __expf(mA - mnA);
        const float cB = __expf(mB - mnB);
        float suA = 0.f, suB = 0.f;
#pragma unroll
        for (int nt = 0; nt < 8; nt++) {
            sacc[nt][0] = __expf(sacc[nt][0] - mnA);
            sacc[nt][1] = __expf(sacc[nt][1] - mnA);
            sacc[nt][2] = __expf(sacc[nt][2] - mnB);
            sacc[nt][3] = __expf(sacc[nt][3] - mnB);
            suA += sacc[nt][0] + sacc[nt][1];
            suB += sacc[nt][2] + sacc[nt][3];
        }
        suA += __shfl_xor_sync(0xffffffffu, suA, 1);
        suA += __shfl_xor_sync(0xffffffffu, suA, 2);
        suB += __shfl_xor_sync(0xffffffffu, suB, 1);
        suB += __shfl_xor_sync(0xffffffffu, suB, 2);
        lA = lA * cA + suA;
        lB = lB * cB + suB;
        mA = mnA;
        mB = mnB;
#pragma unroll
        for (int nt = 0; nt < 8; nt++) {
            oacc[nt][0] *= cA; oacc[nt][1] *= cA;
            oacc[nt][2] *= cB; oacc[nt][3] *= cB;
        }

        // ---- P A-fragments DIRECT from registers (no smem round-trip).
        // For k-step s (keys 16s..16s+15):
        //   af[0] = P[gq][16s+2t,+1]   = sacc[2s][0..1]
        //   af[1] = P[gq+8][16s+2t,+1] = sacc[2s][2..3]
        //   af[2] = P[gq][16s+8+2t,+1] = sacc[2s+1][0..1]
        //   af[3] = P[gq+8][...]       = sacc[2s+1][2..3]
        uint32_t pf[4][4];
#pragma unroll
        for (int s = 0; s < 4; s++) {
            pf[s][0] = pack_bf16x2(sacc[2 * s][0],     sacc[2 * s][1]);
            pf[s][1] = pack_bf16x2(sacc[2 * s][2],     sacc[2 * s][3]);
            pf[s][2] = pack_bf16x2(sacc[2 * s + 1][0], sacc[2 * s + 1][1]);
            pf[s][3] = pack_bf16x2(sacc[2 * s + 1][2], sacc[2 * s + 1][3]);
        }

        // ---- O += P V  (A=P from registers; B=VT ldmatrix)
#pragma unroll
        for (int s = 0; s < 4; s++) {
            const uint32_t ks = (uint32_t)s * 32u;
#pragma unroll
            for (int ntp = 0; ntp < 4; ntp++) {
                uint32_t bq[4];
                ldsm_x4(bq, svw[b] + boffA[ntp] + ks);
                mma_bf16(oacc[2 * ntp],     pf[s], bq);
                mma_bf16(oacc[2 * ntp + 1], pf[s], bq + 2);
            }
        }
        __syncthreads();
        if (kt + 2 < NT) issue(kt + 2, b);
        else CP_COMMIT();
    }

    // ---- Normalize + write O as bf16
    const float iA = 1.f / lA;
    const float iB = 1.f / lB;
    __nv_bfloat16* Og = O + ((size_t)grp * SLEN + qb * 128 + r0) * HEADDIM;
#pragma unroll
    for (int nt = 0; nt < 8; nt++) {
        const int cb = nt * 8 + 2 * t;
        uint32_t wA = pack_bf16x2(oacc[nt][0] * iA, oacc[nt][1] * iA);
        uint32_t wB = pack_bf16x2(oacc[nt][2] * iB, oacc[nt][3] * iB);
        *reinterpret_cast<uint32_t*>(Og + (size_t)gq * HEADDIM + cb) = wA;
        *reinterpret_cast<uint32_t*>(Og + (size_t)(gq + 8) * HEADDIM + cb) = wB;
    }
}

// ---------------------------------------------------------------------------
// Fused residual + LayerNorm (unchanged)
// ---------------------------------------------------------------------------
__global__ __launch_bounds__(256) void ln_kernel(
    const float* __restrict__ x, const float* __restrict__ p,
    const float* __restrict__ gamma, const float* __restrict__ beta,
    float* __restrict__ out)
{
    const int row = blockIdx.x;
    const int t = threadIdx.x;
    const size_t base = (size_t)row * DMODEL + t * 4;

    float4 xv = *(const float4*)(x + base);
    float4 pv = *(const float4*)(p + base);
    float v0 = xv.x + pv.x, v1 = xv.y + pv.y, v2 = xv.z + pv.z, v3 = xv.w + pv.w;

    __shared__ float red[8];
    float s = v0 + v1 + v2 + v3;
#pragma unroll
    for (int off = 16; off >= 1; off >>= 1) s += __shfl_xor_sync(0xffffffffu, s, off);
    if ((t & 31) == 0) red[t >> 5] = s;
    __syncthreads();
    float mu = (red[0] + red[1] + red[2] + red[3] +
                red[4] + red[5] + red[6] + red[7]) * (1.f / DMODEL);
    __syncthreads();

    float d0 = v0 - mu, d1 = v1 - mu, d2 = v2 - mu, d3 = v3 - mu;
    float q = d0 * d0 + d1 * d1 + d2 * d2 + d3 * d3;
#pragma unroll
    for (int off = 16; off >= 1; off >>= 1) q += __shfl_xor_sync(0xffffffffu, q, off);
    if ((t & 31) == 0) red[t >> 5] = q;
    __syncthreads();
    float var = (red[0] + red[1] + red[2] + red[3] +
                 red[4] + red[5] + red[6] + red[7]) * (1.f / DMODEL);
    float rs = rsqrtf(var + 1e-5f);

    float4 gv = *(const float4*)(gamma + t * 4);
    float4 bv = *(const float4*)(beta + t * 4);
    float4 ov;
    ov.x = d0 * rs * gv.x + bv.x;
    ov.y = d1 * rs * gv.y + bv.y;
    ov.z = d2 * rs * gv.z + bv.z;
    ov.w = d3 * rs * gv.w + bv.w;
    *(float4*)(out + base) = ov;
}

// ---------------------------------------------------------------------------
// Launch
// ---------------------------------------------------------------------------
extern "C" void kernel_launch(void* const* d_in, const int* in_sizes, int n_in,
                              void* d_out, int out_size)
{
    (void)in_sizes; (void)n_in; (void)out_size;
    const float* q_in  = (const float*)d_in[0];
    const float* k_in  = (const float*)d_in[1];
    const float* v_in  = (const float*)d_in[2];
    const unsigned char* mask = (const unsigned char*)d_in[3];
    const float* Wq = (const float*)d_in[4];
    const float* Wk = (const float*)d_in[5];
    const float* Wv = (const float*)d_in[6];
    const float* Wo = (const float*)d_in[7];
    const float* bo = (const float*)d_in[8];
    const float* gamma = (const float*)d_in[9];
    const float* beta  = (const float*)d_in[10];
    float* out = (float*)d_out;

    float* pP;
    __nv_bfloat16 *pQb, *pKb, *pVb, *pVTb, *pOb, *pQin, *pKin, *pVin;
    __nv_bfloat16 *pWqT, *pWkT, *pWvT, *pWoT;
    cudaGetSymbolAddress((void**)&pP, g_P);
    cudaGetSymbolAddress((void**)&pQb, g_Qb);
    cudaGetSymbolAddress((void**)&pKb, g_Kb);
    cudaGetSymbolAddress((void**)&pVb, g_Vb);
    cudaGetSymbolAddress((void**)&pVTb, g_VTb);
    cudaGetSymbolAddress((void**)&pOb, g_Ob);
    cudaGetSymbolAddress((void**)&pQin, g_Qin);
    cudaGetSymbolAddress((void**)&pKin, g_Kin);
    cudaGetSymbolAddress((void**)&pVin, g_Vin);
    cudaGetSymbolAddress((void**)&pWqT, g_WqT);
    cudaGetSymbolAddress((void**)&pWkT, g_WkT);
    cudaGetSymbolAddress((void**)&pWvT, g_WvT);
    cudaGetSymbolAddress((void**)&pWoT, g_WoT);

    cudaFuncSetAttribute(gemm_bf16_qkv, cudaFuncAttributeMaxDynamicSharedMemorySize, GEMM_SMEM);
    cudaFuncSetAttribute(gemm_bf16_out, cudaFuncAttributeMaxDynamicSharedMemorySize, GEMM_SMEM);
    cudaFuncSetAttribute(attn_bf16, cudaFuncAttributeMaxDynamicSharedMemorySize, ATT_SMEM);

    // launch 0: fused weight transposes (z selects matrix)
    dim3 tgrid(DMODEL / 32, DMODEL / 32, 4);
    dim3 tblk(32, 8);
    transpose1024_bf16_fused<<<tgrid, tblk>>>(Wq, Wk, Wv, Wo, pWqT, pWkT, pWvT, pWoT);

    // launch 1: fused input conversion
    dim3 cgrid(NROWS * DMODEL / (256 * 8), 3);
    cvt_bf16_fused<<<cgrid, 256>>>(q_in, k_in, v_in, pQin, pKin, pVin);

    // launch 2: batched Q/K/V projections
    dim3 ggrid3(DMODEL / 128, NROWS / 128, 3);
    gemm_bf16_qkv<<<ggrid3, 256, GEMM_SMEM>>>(
        pQin, pKin, pVin, pWqT, pWkT, pWvT, pQb, pKb, pVb,
        NROWS, DMODEL, DMODEL);

    // launch 3: V -> VT per group
    dim3 vgrid(SLEN / 32, HEADDIM / 32, NGROUPS);
    vtranspose_bf16<<<vgrid, tblk>>>(pVb, pVTb);

    // launch 4: attention
    dim3 agrid(SLEN / 128, NGROUPS);
    attn_bf16<<<agrid, 256, ATT_SMEM>>>(pQb, pKb, pVTb, mask, pOb);

    // launch 5: output projection (+bias, fp32 out)
    dim3 ggrid1(DMODEL / 128, NROWS / 128);
    gemm_bf16_out<<<ggrid1, 256, GEMM_SMEM>>>(pOb, pWoT, bo, pP, NROWS, DMODEL, DMODEL);

    // launch 6: residual + LayerNorm
    ln_kernel<<<NROWS, 256>>>(q_in, pP, gamma, beta, out);
}

// round 13
// speedup vs baseline: 1.1915x; 1.0538x over previous
#include <cuda_runtime.h>
#include <cuda_bf16.h>
#include <math.h>
#include <cstdint>

// Problem constants
#define BATCH   2
#define SLEN    2048
#define DMODEL  1024
#define NHEADS  16
#define HEADDIM 64
#define NROWS   (BATCH * SLEN)      // 4096
#define NGROUPS (BATCH * NHEADS)    // 32 reshaped "heads"

// Scratch (allocation-free rule: __device__ globals)
__device__ float g_P[NROWS * DMODEL];
__device__ __nv_bfloat16 g_Qb[NROWS * DMODEL];
__device__ __nv_bfloat16 g_Kb[NROWS * DMODEL];
__device__ __nv_bfloat16 g_Vb[NROWS * DMODEL];
__device__ __nv_bfloat16 g_VTb[NROWS * DMODEL];  // per-group transposed V
__device__ __nv_bfloat16 g_Ob[NROWS * DMODEL];
__device__ __nv_bfloat16 g_Qin[NROWS * DMODEL];
__device__ __nv_bfloat16 g_Kin[NROWS * DMODEL];
__device__ __nv_bfloat16 g_Vin[NROWS * DMODEL];
__device__ __nv_bfloat16 g_WqT[DMODEL * DMODEL];
__device__ __nv_bfloat16 g_WkT[DMODEL * DMODEL];
__device__ __nv_bfloat16 g_WvT[DMODEL * DMODEL];
__device__ __nv_bfloat16 g_WoT[DMODEL * DMODEL];
__device__ unsigned long long g_Mb[BATCH * SLEN * (SLEN / 64)];  // packed mask bits

// ---------------------------------------------------------------------------
// Helpers (sm_80+ only — compute_103 rejects 'a'-gated PTX like tcgen05)
// ---------------------------------------------------------------------------
__device__ __forceinline__ uint32_t smem_u32(const void* p) {
    uint32_t a;
    asm("{ .reg .u64 t; cvta.to.shared.u64 t, %1; cvt.u32.u64 %0, t; }"
        : "=r"(a) : "l"(p));
    return a;
}

__device__ __forceinline__ void cp_async16(uint32_t saddr, const void* gaddr) {
    asm volatile("cp.async.cg.shared.global [%0], [%1], 16;"
                 :: "r"(saddr), "l"(gaddr) : "memory");
}
#define CP_COMMIT() asm volatile("cp.async.commit_group;" ::: "memory")
#define CP_WAIT1()  asm volatile("cp.async.wait_group 1;" ::: "memory")

__device__ __forceinline__ void mma_bf16(float* d, const uint32_t* a, const uint32_t* b) {
    asm volatile(
        "mma.sync.aligned.m16n8k16.row.col.f32.bf16.bf16.f32 "
        "{%0,%1,%2,%3}, {%4,%5,%6,%7}, {%8,%9}, {%0,%1,%2,%3};"
        : "+f"(d[0]), "+f"(d[1]), "+f"(d[2]), "+f"(d[3])
        : "r"(a[0]), "r"(a[1]), "r"(a[2]), "r"(a[3]), "r"(b[0]), "r"(b[1]));
}

__device__ __forceinline__ void ldsm_x4(uint32_t* r, uint32_t saddr) {
    asm volatile("ldmatrix.sync.aligned.m8n8.x4.shared.b16 {%0,%1,%2,%3}, [%4];"
                 : "=r"(r[0]), "=r"(r[1]), "=r"(r[2]), "=r"(r[3]) : "r"(saddr));
}

__device__ __forceinline__ uint32_t pack_bf16x2(float lo, float hi) {
    __nv_bfloat162 h = __floats2bfloat162_rn(lo, hi);
    return *reinterpret_cast<uint32_t*>(&h);
}

// ---------------------------------------------------------------------------
// Mask bit-pack: mask bytes (0/1) -> one uint64 per (row, 64-key word).
// word idx w covers bytes [w*64, w*64+64); bit j = mask[w*64 + j] != 0.
// bits4(u) gathers the 4 byte-LSBs of a uint32: bits 24..27 of u*0x01020408
// are b0..b3 (all cross terms land below bit 24 or overflow; no carries).
// ---------------------------------------------------------------------------
__global__ __launch_bounds__(256) void mask_pack(
    const unsigned char* __restrict__ m, unsigned long long* __restrict__ mb)
{
    const int idx = blockIdx.x * 256 + threadIdx.x;   // word index
    const uint4* p4 = reinterpret_cast<const uint4*>(m + (size_t)idx * 64);
    unsigned long long w = 0;
#pragma unroll
    for (int q = 0; q < 4; q++) {
        uint4 v = p4[q];
        uint32_t b = ((v.x * 0x01020408u) >> 24) & 0xFu;
        b |= (((v.y * 0x01020408u) >> 24) & 0xFu) << 4;
        b |= (((v.z * 0x01020408u) >> 24) & 0xFu) << 8;
        b |= (((v.w * 0x01020408u) >> 24) & 0xFu) << 12;
        w |= (unsigned long long)b << (q * 16);
    }
    mb[idx] = w;
}

// ---------------------------------------------------------------------------
// Fused fp32 -> bf16 conversion of q/k/v inputs (blockIdx.y selects tensor)
// ---------------------------------------------------------------------------
__global__ __launch_bounds__(256) void cvt_bf16_fused(
    const float* __restrict__ x0, const float* __restrict__ x1,
    const float* __restrict__ x2,
    __nv_bfloat16* __restrict__ y0, __nv_bfloat16* __restrict__ y1,
    __nv_bfloat16* __restrict__ y2)
{
    const int z = blockIdx.y;
    const float* x = (z == 0) ? x0 : (z == 1) ? x1 : x2;
    __nv_bfloat16* y = (z == 0) ? y0 : (z == 1) ? y1 : y2;
    const size_t i = ((size_t)blockIdx.x * 256 + threadIdx.x) * 8;
    float4 a = *(const float4*)(x + i);
    float4 b = *(const float4*)(x + i + 4);
    __nv_bfloat162* yp = reinterpret_cast<__nv_bfloat162*>(y + i);
    yp[0] = __floats2bfloat162_rn(a.x, a.y);
    yp[1] = __floats2bfloat162_rn(a.z, a.w);
    yp[2] = __floats2bfloat162_rn(b.x, b.y);
    yp[3] = __floats2bfloat162_rn(b.z, b.w);
}

// ---------------------------------------------------------------------------
// Fused weight transpose (fp32 -> bf16): Wt[n][k] = bf16(W[k][n]).
// ---------------------------------------------------------------------------
__global__ __launch_bounds__(256) void transpose1024_bf16_fused(
    const float* __restrict__ W0, const float* __restrict__ W1,
    const float* __restrict__ W2, const float* __restrict__ W3,
    __nv_bfloat16* __restrict__ T0, __nv_bfloat16* __restrict__ T1,
    __nv_bfloat16* __restrict__ T2, __nv_bfloat16* __restrict__ T3)
{
    const int z = blockIdx.z;
    const float* W = (z == 0) ? W0 : (z == 1) ? W1 : (z == 2) ? W2 : W3;
    __nv_bfloat16* Wt = (z == 0) ? T0 : (z == 1) ? T1 : (z == 2) ? T2 : T3;

    __shared__ float t[32][33];
    const int bx = blockIdx.x * 32, by = blockIdx.y * 32;
    const int x = threadIdx.x, y = threadIdx.y;   // 32 x 8
#pragma unroll
    for (int i = 0; i < 32; i += 8)
        t[y + i][x] = W[(size_t)(by + y + i) * DMODEL + bx + x];
    __syncthreads();
#pragma unroll
    for (int i = 0; i < 32; i += 8)
        Wt[(size_t)(bx + y + i) * DMODEL + by + x] = __float2bfloat16_rn(t[x][y + i]);
}

// ---------------------------------------------------------------------------
// V transpose per group (bf16): V[g][s][d] -> VT[g][d][s]
// ---------------------------------------------------------------------------
__global__ __launch_bounds__(256) void vtranspose_bf16(
    const __nv_bfloat16* __restrict__ V, __nv_bfloat16* __restrict__ VT)
{
    __shared__ __nv_bfloat16 t[32][34];
    const int g = blockIdx.z;
    const int s0 = blockIdx.x * 32, d0 = blockIdx.y * 32;
    const int x = threadIdx.x, y = threadIdx.y;   // 32 x 8
    const __nv_bfloat16* Vg = V + (size_t)g * SLEN * HEADDIM;
    __nv_bfloat16* VTg = VT + (size_t)g * SLEN * HEADDIM;
#pragma unroll
    for (int i = 0; i < 32; i += 8)
        t[y + i][x] = Vg[(size_t)(s0 + y + i) * HEADDIM + d0 + x];
    __syncthreads();
#pragma unroll
    for (int i = 0; i < 32; i += 8)
        VTg[(size_t)(d0 + y + i) * SLEN + s0 + x] = t[x][y + i];
}

// ---------------------------------------------------------------------------
// HMMA bf16 GEMM (R8-validated): CTA 128x128, BK=64, 8 warps (4x2),
// warp 32x64, 2-stage cp.async, ldmatrix fragments. Smem 73728 B.
// ---------------------------------------------------------------------------
#define KSW 36
#define TILE_WORDS (128 * KSW)
#define GEMM_SMEM (4 * TILE_WORDS * 4)   // 73728 B

__global__ __launch_bounds__(256) void gemm_bf16_qkv(
    const __nv_bfloat16* __restrict__ A0, const __nv_bfloat16* __restrict__ A1,
    const __nv_bfloat16* __restrict__ A2,
    const __nv_bfloat16* __restrict__ B0, const __nv_bfloat16* __restrict__ B1,
    const __nv_bfloat16* __restrict__ B2,
    __nv_bfloat16* __restrict__ C0, __nv_bfloat16* __restrict__ C1,
    __nv_bfloat16* __restrict__ C2, int M, int N, int K)
{
    extern __shared__ uint32_t shw[];
    uint32_t* sA[2] = { shw,              shw + 2 * TILE_WORDS };
    uint32_t* sB[2] = { shw + TILE_WORDS, shw + 3 * TILE_WORDS };

    const int z = blockIdx.z;
    const __nv_bfloat16* A = (z == 0) ? A0 : (z == 1) ? A1 : A2;
    const __nv_bfloat16* Bt = (z == 0) ? B0 : (z == 1) ? B1 : B2;
    __nv_bfloat16* C = (z == 0) ? C0 : (z == 1) ? C1 : C2;

    const int tid = threadIdx.x;
    const int wid = tid >> 5;
    const int lane = tid & 31;
    const int mb = (wid & 3) * 32;
    const int nb = (wid >> 2) * 64;
    const int g = lane >> 2;
    const int t = lane & 3;
    const int m0 = blockIdx.y * 128;
    const int n0 = blockIdx.x * 128;

    const int quad = lane >> 3;
    const int within = lane & 7;
    const int arow = (quad & 1) * 8 + within;
    const int acol = (quad >> 1) * 4;
    const int brow = (quad >> 1) * 8 + within;
    const int bcol = (quad & 1) * 4;

    const uint32_t aoff0 = (uint32_t)((mb + arow) * KSW + acol) * 4u;
    const uint32_t aoff1 = (uint32_t)((mb + 16 + arow) * KSW + acol) * 4u;
    uint32_t boff[4];
#pragma unroll
    for (int ntp = 0; ntp < 4; ntp++)
        boff[ntp] = (uint32_t)((nb + ntp * 16 + brow) * KSW + bcol) * 4u;

    const uint32_t saw[2] = { smem_u32(sA[0]), smem_u32(sA[1]) };
    const uint32_t sbw[2] = { smem_u32(sB[0]), smem_u32(sB[1]) };

    float acc[2][8][4];
#pragma unroll
    for (int i = 0; i < 2; i++)
#pragma unroll
        for (int j = 0; j < 8; j++)
#pragma unroll
            for (int q = 0; q < 4; q++) acc[i][j][q] = 0.f;

    const int NCH = K / 64;

    auto issue = [&](int c, int b) {
        const __nv_bfloat16* Ag = A + (size_t)m0 * K + (size_t)c * 64;
        const __nv_bfloat16* Bg = Bt + (size_t)n0 * K + (size_t)c * 64;
#pragma unroll
        for (int i = 0; i < 4; i++) {
            const int u = tid + 256 * i;
            const int row = u >> 3;
            const int seg = u & 7;
            const uint32_t so = (uint32_t)(row * KSW + seg * 4) * 4u;
            cp_async16(saw[b] + so, Ag + (size_t)row * K + seg * 8);
            cp_async16(sbw[b] + so, Bg + (size_t)row * K + seg * 8);
        }
        CP_COMMIT();
    };

    issue(0, 0);
    issue(1, 1);

    for (int c = 0; c < NCH; c++) {
        const int b = c & 1;
        CP_WAIT1();
        __syncthreads();
#pragma unroll
        for (int s = 0; s < 4; s++) {
            const uint32_t ks = (uint32_t)s * 32u;
            uint32_t af0[4], af1[4];
            ldsm_x4(af0, saw[b] + aoff0 + ks);
            ldsm_x4(af1, saw[b] + aoff1 + ks);
#pragma unroll
            for (int ntp = 0; ntp < 4; ntp++) {
                uint32_t bq[4];
                ldsm_x4(bq, sbw[b] + boff[ntp] + ks);
                mma_bf16(acc[0][2 * ntp],     af0, bq);
                mma_bf16(acc[1][2 * ntp],     af1, bq);
                mma_bf16(acc[0][2 * ntp + 1], af0, bq + 2);
                mma_bf16(acc[1][2 * ntp + 1], af1, bq + 2);
            }
        }
        __syncthreads();
        if (c + 2 < NCH) issue(c + 2, b);
        else CP_COMMIT();
    }

#pragma unroll
    for (int mt = 0; mt < 2; mt++) {
        const int r = m0 + mb + mt * 16 + g;
#pragma unroll
        for (int nt = 0; nt < 8; nt++) {
            const int cx = n0 + nb + nt * 8 + 2 * t;
            uint32_t w0 = pack_bf16x2(acc[mt][nt][0], acc[mt][nt][1]);
            uint32_t w1 = pack_bf16x2(acc[mt][nt][2], acc[mt][nt][3]);
            *reinterpret_cast<uint32_t*>(C + (size_t)r * N + cx) = w0;
            *reinterpret_cast<uint32_t*>(C + (size_t)(r + 8) * N + cx) = w1;
        }
    }
}

__global__ __launch_bounds__(256) void gemm_bf16_out(
    const __nv_bfloat16* __restrict__ A, const __nv_bfloat16* __restrict__ Bt,
    const float* __restrict__ bias, float* __restrict__ C,
    int M, int N, int K)
{
    extern __shared__ uint32_t shw[];
    uint32_t* sA[2] = { shw,              shw + 2 * TILE_WORDS };
    uint32_t* sB[2] = { shw + TILE_WORDS, shw + 3 * TILE_WORDS };

    const int tid = threadIdx.x;
    const int wid = tid >> 5;
    const int lane = tid & 31;
    const int mb = (wid & 3) * 32;
    const int nb = (wid >> 2) * 64;
    const int g = lane >> 2;
    const int t = lane & 3;
    const int m0 = blockIdx.y * 128;
    const int n0 = blockIdx.x * 128;

    const int quad = lane >> 3;
    const int within = lane & 7;
    const int arow = (quad & 1) * 8 + within;
    const int acol = (quad >> 1) * 4;
    const int brow = (quad >> 1) * 8 + within;
    const int bcol = (quad & 1) * 4;

    const uint32_t aoff0 = (uint32_t)((mb + arow) * KSW + acol) * 4u;
    const uint32_t aoff1 = (uint32_t)((mb + 16 + arow) * KSW + acol) * 4u;
    uint32_t boff[4];
#pragma unroll
    for (int ntp = 0; ntp < 4; ntp++)
        boff[ntp] = (uint32_t)((nb + ntp * 16 + brow) * KSW + bcol) * 4u;

    const uint32_t saw[2] = { smem_u32(sA[0]), smem_u32(sA[1]) };
    const uint32_t sbw[2] = { smem_u32(sB[0]), smem_u32(sB[1]) };

    float acc[2][8][4];
#pragma unroll
    for (int i = 0; i < 2; i++)
#pragma unroll
        for (int j = 0; j < 8; j++)
#pragma unroll
            for (int q = 0; q < 4; q++) acc[i][j][q] = 0.f;

    const int NCH = K / 64;

    auto issue = [&](int c, int b) {
        const __nv_bfloat16* Ag = A + (size_t)m0 * K + (size_t)c * 64;
        const __nv_bfloat16* Bg = Bt + (size_t)n0 * K + (size_t)c * 64;
#pragma unroll
        for (int i = 0; i < 4; i++) {
            const int u = tid + 256 * i;
            const int row = u >> 3;
            const int seg = u & 7;
            const uint32_t so = (uint32_t)(row * KSW + seg * 4) * 4u;
            cp_async16(saw[b] + so, Ag + (size_t)row * K + seg * 8);
            cp_async16(sbw[b] + so, Bg + (size_t)row * K + seg * 8);
        }
        CP_COMMIT();
    };

    issue(0, 0);
    issue(1, 1);

    for (int c = 0; c < NCH; c++) {
        const int b = c & 1;
        CP_WAIT1();
        __syncthreads();
#pragma unroll
        for (int s = 0; s < 4; s++) {
            const uint32_t ks = (uint32_t)s * 32u;
            uint32_t af0[4], af1[4];
            ldsm_x4(af0, saw[b] + aoff0 + ks);
            ldsm_x4(af1, saw[b] + aoff1 + ks);
#pragma unroll
            for (int ntp = 0; ntp < 4; ntp++) {
                uint32_t bq[4];
                ldsm_x4(bq, sbw[b] + boff[ntp] + ks);
                mma_bf16(acc[0][2 * ntp],     af0, bq);
                mma_bf16(acc[1][2 * ntp],     af1, bq);
                mma_bf16(acc[0][2 * ntp + 1], af0, bq + 2);
                mma_bf16(acc[1][2 * ntp + 1], af1, bq + 2);
            }
        }
        __syncthreads();
        if (c + 2 < NCH) issue(c + 2, b);
        else CP_COMMIT();
    }

#pragma unroll
    for (int mt = 0; mt < 2; mt++) {
        const int r = m0 + mb + mt * 16 + g;
#pragma unroll
        for (int nt = 0; nt < 8; nt++) {
            const int cx = n0 + nb + nt * 8 + 2 * t;
            const float b0 = __ldg(&bias[cx]);
            const float b1 = __ldg(&bias[cx + 1]);
            float2 v0, v1;
            v0.x = acc[mt][nt][0] + b0; v0.y = acc[mt][nt][1] + b1;
            v1.x = acc[mt][nt][2] + b0; v1.y = acc[mt][nt][3] + b1;
            *(float2*)(C + (size_t)r * N + cx) = v0;
            *(float2*)(C + (size_t)(r + 8) * N + cx) = v1;
        }
    }
}

// ---------------------------------------------------------------------------
// bf16 HMMA flash attention. Q,K bf16 [32][2048][64]; VT bf16 [32][64][2048].
// CTA: 128 Q rows x 1 group, 8 warps, K-tiles of 64 keys, 2-stage cp.async.
// P stays in registers (R12). R13: mask consumed as packed bits — 2 uint64
// loads + warp vote per tile; all-clear tiles take a scale-only fast path.
// ---------------------------------------------------------------------------
#define AKW 36
#define ATT_TILE (64 * AKW)
#define ATT_SMEM (4 * ATT_TILE * 4)   // 36864 B

__global__ __launch_bounds__(256) void attn_bf16(
    const __nv_bfloat16* __restrict__ Q, const __nv_bfloat16* __restrict__ K,
    const __nv_bfloat16* __restrict__ VT,
    const unsigned long long* __restrict__ maskbits,
    __nv_bfloat16* __restrict__ O)
{
    extern __shared__ uint32_t smw[];

    const int tid = threadIdx.x;
    const int wid = tid >> 5;
    const int lane = tid & 31;
    const int gq = lane >> 2;
    const int t = lane & 3;
    const int qb = blockIdx.x;
    const int grp = blockIdx.y;
    const int r0 = wid * 16;

    const int quad = lane >> 3;
    const int within = lane & 7;
    const int arow = (quad & 1) * 8 + within;
    const int acol = (quad >> 1) * 4;
    const int brow = (quad >> 1) * 8 + within;
    const int bcol = (quad & 1) * 4;

    uint32_t boffA[4];
#pragma unroll
    for (int ntp = 0; ntp < 4; ntp++)
        boffA[ntp] = (uint32_t)((ntp * 16 + brow) * AKW + bcol) * 4u;

    const uint32_t skw[2] = { smem_u32(smw), smem_u32(smw + ATT_TILE) };
    const uint32_t svw[2] = { smem_u32(smw + 2 * ATT_TILE), smem_u32(smw + 3 * ATT_TILE) };

    const __nv_bfloat16* Qg = Q + ((size_t)grp * SLEN + qb * 128 + r0) * HEADDIM;
    const __nv_bfloat16* Kg = K + (size_t)grp * SLEN * HEADDIM;
    const __nv_bfloat16* VTg = VT + (size_t)grp * SLEN * HEADDIM;
    // packed mask: [batch][row][word]; word kt covers keys [kt*64, kt*64+64)
    const unsigned long long* mw =
        maskbits + ((size_t)(grp % BATCH) * SLEN + (size_t)(qb * 128 + r0)) * (SLEN / 64);

    auto issue = [&](int kt, int b) {
#pragma unroll
        for (int i = 0; i < 2; i++) {
            const int u = tid + 256 * i;
            const int row = u >> 3;
            const int seg = u & 7;
            const uint32_t so = (uint32_t)(row * AKW + seg * 4) * 4u;
            cp_async16(skw[b] + so, Kg + (size_t)(kt * 64 + row) * HEADDIM + seg * 8);
            cp_async16(svw[b] + so, VTg + (size_t)row * SLEN + kt * 64 + seg * 8);
        }
        CP_COMMIT();
    };

    // ---- Stage Q through the tile-buffer region, build persistent A frags
    uint32_t* sQw = smw + r0 * AKW;
    const uint32_t sq_addr = smem_u32(sQw) + (uint32_t)(arow * AKW + acol) * 4u;
    {
        const int row = lane >> 1;
        const int cs = (lane & 1) * 16;
#pragma unroll
        for (int j = 0; j < 4; j++) {
            uint4 v = *(const uint4*)(Qg + (size_t)row * HEADDIM + (cs + j * 4) * 2);
            *(uint4*)&sQw[row * AKW + cs + j * 4] = v;
        }
    }
    __syncwarp();
    uint32_t qf[4][4];
#pragma unroll
    for (int s = 0; s < 4; s++)
        ldsm_x4(qf[s], sq_addr + (uint32_t)s * 32u);
    __syncthreads();   // Q fragments captured before buffers reused by cp.async

    issue(0, 0);
    issue(1, 1);

    float oacc[8][4];
#pragma unroll
    for (int nt = 0; nt < 8; nt++)
#pragma unroll
        for (int q = 0; q < 4; q++) oacc[nt][q] = 0.f;
    float mA = -INFINITY, mB = -INFINITY, lA = 0.f, lB = 0.f;

    const float scale = 0.125f;
    const int NT = SLEN / 64;

    for (int kt = 0; kt < NT; kt++) {
        const int b = kt & 1;
        CP_WAIT1();
        __syncthreads();

        // ---- S = Q K^T
        float sacc[8][4];
#pragma unroll
        for (int nt = 0; nt < 8; nt++)
#pragma unroll
            for (int q = 0; q < 4; q++) sacc[nt][q] = 0.f;
#pragma unroll
        for (int s = 0; s < 4; s++) {
            const uint32_t ks = (uint32_t)s * 32u;
#pragma unroll
            for (int ntp = 0; ntp < 4; ntp++) {
                uint32_t bq[4];
                ldsm_x4(bq, skw[b] + boffA[ntp] + ks);
                mma_bf16(sacc[2 * ntp],     qf[s], bq);
                mma_bf16(sacc[2 * ntp + 1], qf[s], bq + 2);
            }
        }

        // ---- Mask + scale (packed-bit path)
        const unsigned long long wA = mw[(size_t)gq * (SLEN / 64) + kt];
        const unsigned long long wB = mw[(size_t)(gq + 8) * (SLEN / 64) + kt];
        if (__all_sync(0xffffffffu, (wA | wB) == 0ull)) {
            // fast path: no masked keys in this tile for any row of the warp
#pragma unroll
            for (int nt = 0; nt < 8; nt++) {
                sacc[nt][0] *= scale; sacc[nt][1] *= scale;
                sacc[nt][2] *= scale; sacc[nt][3] *= scale;
            }
        } else {
#pragma unroll
            for (int nt = 0; nt < 8; nt++) {
                const int c0 = nt * 8 + 2 * t;
                sacc[nt][0] = ((wA >> c0) & 1ull) ? -1e9f : sacc[nt][0] * scale;
                sacc[nt][1] = ((wA >> (c0 + 1)) & 1ull) ? -1e9f : sacc[nt][1] * scale;
                sacc[nt][2] = ((wB >> c0) & 1ull) ? -1e9f : sacc[nt][2] * scale;
                sacc[nt][3] = ((wB >> (c0 + 1)) & 1ull) ? -1e9f : sacc[nt][3] * scale;
            }
        }

        // ---- Online softmax
        float mxA = -INFINITY, mxB = -INFINITY;
#pragma unroll
        for (int nt = 0; nt < 8; nt++) {
            mxA = fmaxf(mxA, fmaxf(sacc[nt][0], sacc[nt][1]));
            mxB = fmaxf(mxB, fmaxf(sacc[nt][2], sacc[nt][3]));
        }
        mxA = fmaxf(mxA, __shfl_xor_sync(0xffffffffu, mxA, 1));
        mxA = fmaxf(mxA, __shfl_xor_sync(0xffffffffu, mxA, 2));
        mxB = fmaxf(mxB, __shfl_xor_sync(0xffffffffu, mxB, 1));
        mxB = fmaxf(mxB, __shfl_xor_sync(0xffffffffu, mxB, 2));

        const float mnA = fmaxf(mA, mxA);
        const float mnB = fmaxf(mB, mxB);
        const float cA = __expf(mA - mnA);
        const float cB = __expf(mB - mnB);
        float suA = 0.f, suB = 0.f;
#pragma unroll
        for (int nt = 0; nt < 8; nt++) {
            sacc[nt][0] = __expf(sacc[nt][0] - mnA);
            sacc[nt][1] = __expf(sacc[nt][1] - mnA);
            sacc[nt][2] = __expf(sacc[nt][2] - mnB);
            sacc[nt][3] = __expf(sacc[nt][3] - mnB);
            suA += sacc[nt][0] + sacc[nt][1];
            suB += sacc[nt][2] + sacc[nt][3];
        }
        suA += __shfl_xor_sync(0xffffffffu, suA, 1);
        suA += __shfl_xor_sync(0xffffffffu, suA, 2);
        suB += __shfl_xor_sync(0xffffffffu, suB, 1);
        suB += __shfl_xor_sync(0xffffffffu, suB, 2);
        lA = lA * cA + suA;
        lB = lB * cB + suB;
        mA = mnA;
        mB = mnB;
#pragma unroll
        for (int nt = 0; nt < 8; nt++) {
            oacc[nt][0] *= cA; oacc[nt][1] *= cA;
            oacc[nt][2] *= cB; oacc[nt][3] *= cB;
        }

        // ---- P A-fragments direct from registers (R12-validated mapping)
        uint32_t pf[4][4];
#pragma unroll
        for (int s = 0; s < 4; s++) {
            pf[s][0] = pack_bf16x2(sacc[2 * s][0],     sacc[2 * s][1]);
            pf[s][1] = pack_bf16x2(sacc[2 * s][2],     sacc[2 * s][3]);
            pf[s][2] = pack_bf16x2(sacc[2 * s + 1][0], sacc[2 * s + 1][1]);
            pf[s][3] = pack_bf16x2(sacc[2 * s + 1][2], sacc[2 * s + 1][3]);
        }

        // ---- O += P V  (A=P from registers; B=VT ldmatrix)
#pragma unroll
        for (int s = 0; s < 4; s++) {
            const uint32_t ks = (uint32_t)s * 32u;
#pragma unroll
            for (int ntp = 0; ntp < 4; ntp++) {
                uint32_t bq[4];
                ldsm_x4(bq, svw[b] + boffA[ntp] + ks);
                mma_bf16(oacc[2 * ntp],     pf[s], bq);
                mma_bf16(oacc[2 * ntp + 1], pf[s], bq + 2);
            }
        }
        __syncthreads();
        if (kt + 2 < NT) issue(kt + 2, b);
        else CP_COMMIT();
    }

    // ---- Normalize + write O as bf16
    const float iA = 1.f / lA;
    const float iB = 1.f / lB;
    __nv_bfloat16* Og = O + ((size_t)grp * SLEN + qb * 128 + r0) * HEADDIM;
#pragma unroll
    for (int nt = 0; nt < 8; nt++) {
        const int cb = nt * 8 + 2 * t;
        uint32_t wA = pack_bf16x2(oacc[nt][0] * iA, oacc[nt][1] * iA);
        uint32_t wB = pack_bf16x2(oacc[nt][2] * iB, oacc[nt][3] * iB);
        *reinterpret_cast<uint32_t*>(Og + (size_t)gq * HEADDIM + cb) = wA;
        *reinterpret_cast<uint32_t*>(Og + (size_t)(gq + 8) * HEADDIM + cb) = wB;
    }
}

// ---------------------------------------------------------------------------
// Fused residual + LayerNorm (unchanged)
// ---------------------------------------------------------------------------
__global__ __launch_bounds__(256) void ln_kernel(
    const float* __restrict__ x, const float* __restrict__ p,
    const float* __restrict__ gamma, const float* __restrict__ beta,
    float* __restrict__ out)
{
    const int row = blockIdx.x;
    const int t = threadIdx.x;
    const size_t base = (size_t)row * DMODEL + t * 4;

    float4 xv = *(const float4*)(x + base);
    float4 pv = *(const float4*)(p + base);
    float v0 = xv.x + pv.x, v1 = xv.y + pv.y, v2 = xv.z + pv.z, v3 = xv.w + pv.w;

    __shared__ float red[8];
    float s = v0 + v1 + v2 + v3;
#pragma unroll
    for (int off = 16; off >= 1; off >>= 1) s += __shfl_xor_sync(0xffffffffu, s, off);
    if ((t & 31) == 0) red[t >> 5] = s;
    __syncthreads();
    float mu = (red[0] + red[1] + red[2] + red[3] +
                red[4] + red[5] + red[6] + red[7]) * (1.f / DMODEL);
    __syncthreads();

    float d0 = v0 - mu, d1 = v1 - mu, d2 = v2 - mu, d3 = v3 - mu;
    float q = d0 * d0 + d1 * d1 + d2 * d2 + d3 * d3;
#pragma unroll
    for (int off = 16; off >= 1; off >>= 1) q += __shfl_xor_sync(0xffffffffu, q, off);
    if ((t & 31) == 0) red[t >> 5] = q;
    __syncthreads();
    float var = (red[0] + red[1] + red[2] + red[3] +
                 red[4] + red[5] + red[6] + red[7]) * (1.f / DMODEL);
    float rs = rsqrtf(var + 1e-5f);

    float4 gv = *(const float4*)(gamma + t * 4);
    float4 bv = *(const float4*)(beta + t * 4);
    float4 ov;
    ov.x = d0 * rs * gv.x + bv.x;
    ov.y = d1 * rs * gv.y + bv.y;
    ov.z = d2 * rs * gv.z + bv.z;
    ov.w = d3 * rs * gv.w + bv.w;
    *(float4*)(out + base) = ov;
}

// ---------------------------------------------------------------------------
// Launch
// ---------------------------------------------------------------------------
extern "C" void kernel_launch(void* const* d_in, const int* in_sizes, int n_in,
                              void* d_out, int out_size)
{
    (void)in_sizes; (void)n_in; (void)out_size;
    const float* q_in  = (const float*)d_in[0];
    const float* k_in  = (const float*)d_in[1];
    const float* v_in  = (const float*)d_in[2];
    const unsigned char* mask = (const unsigned char*)d_in[3];
    const float* Wq = (const float*)d_in[4];
    const float* Wk = (const float*)d_in[5];
    const float* Wv = (const float*)d_in[6];
    const float* Wo = (const float*)d_in[7];
    const float* bo = (const float*)d_in[8];
    const float* gamma = (const float*)d_in[9];
    const float* beta  = (const float*)d_in[10];
    float* out = (float*)d_out;

    float* pP;
    __nv_bfloat16 *pQb, *pKb, *pVb, *pVTb, *pOb, *pQin, *pKin, *pVin;
    __nv_bfloat16 *pWqT, *pWkT, *pWvT, *pWoT;
    unsigned long long* pMb;
    cudaGetSymbolAddress((void**)&pP, g_P);
    cudaGetSymbolAddress((void**)&pQb, g_Qb);
    cudaGetSymbolAddress((void**)&pKb, g_Kb);
    cudaGetSymbolAddress((void**)&pVb, g_Vb);
    cudaGetSymbolAddress((void**)&pVTb, g_VTb);
    cudaGetSymbolAddress((void**)&pOb, g_Ob);
    cudaGetSymbolAddress((void**)&pQin, g_Qin);
    cudaGetSymbolAddress((void**)&pKin, g_Kin);
    cudaGetSymbolAddress((void**)&pVin, g_Vin);
    cudaGetSymbolAddress((void**)&pWqT, g_WqT);
    cudaGetSymbolAddress((void**)&pWkT, g_WkT);
    cudaGetSymbolAddress((void**)&pWvT, g_WvT);
    cudaGetSymbolAddress((void**)&pWoT, g_WoT);
    cudaGetSymbolAddress((void**)&pMb, g_Mb);

    cudaFuncSetAttribute(gemm_bf16_qkv, cudaFuncAttributeMaxDynamicSharedMemorySize, GEMM_SMEM);
    cudaFuncSetAttribute(gemm_bf16_out, cudaFuncAttributeMaxDynamicSharedMemorySize, GEMM_SMEM);
    cudaFuncSetAttribute(attn_bf16, cudaFuncAttributeMaxDynamicSharedMemorySize, ATT_SMEM);

    // launch 0: fused weight transposes
    dim3 tgrid(DMODEL / 32, DMODEL / 32, 4);
    dim3 tblk(32, 8);
    transpose1024_bf16_fused<<<tgrid, tblk>>>(Wq, Wk, Wv, Wo, pWqT, pWkT, pWvT, pWoT);

    // launch 1: fused input conversion
    dim3 cgrid(NROWS * DMODEL / (256 * 8), 3);
    cvt_bf16_fused<<<cgrid, 256>>>(q_in, k_in, v_in, pQin, pKin, pVin);

    // launch 2: mask bit-pack (131072 words)
    mask_pack<<<BATCH * SLEN * (SLEN / 64) / 256, 256>>>(mask, pMb);

    // launch 3: batched Q/K/V projections
    dim3 ggrid3(DMODEL / 128, NROWS / 128, 3);
    gemm_bf16_qkv<<<ggrid3, 256, GEMM_SMEM>>>(
        pQin, pKin, pVin, pWqT, pWkT, pWvT, pQb, pKb, pVb,
        NROWS, DMODEL, DMODEL);

    // launch 4: V -> VT per group
    dim3 vgrid(SLEN / 32, HEADDIM / 32, NGROUPS);
    vtranspose_bf16<<<vgrid, tblk>>>(pVb, pVTb);

    // launch 5: attention (packed-bit mask)
    dim3 agrid(SLEN / 128, NGROUPS);
    attn_bf16<<<agrid, 256, ATT_SMEM>>>(pQb, pKb, pVTb, pMb, pOb);

    // launch 6: output projection (+bias, fp32 out)
    dim3 ggrid1(DMODEL / 128, NROWS / 128);
    gemm_bf16_out<<<ggrid1, 256, GEMM_SMEM>>>(pOb, pWoT, bo, pP, NROWS, DMODEL, DMODEL);

    // launch 7: residual + LayerNorm
    ln_kernel<<<NROWS, 256>>>(q_in, pP, gamma, beta, out);
}